// round 11
// baseline (speedup 1.0000x reference)
#include <cuda_runtime.h>

#define NPIX 22500
#define NB 32
#define NCHUNK 9
#define CHUNK 2500   // 22500 / 9
#define TPB 256
#define HB 64
#define LOB (-3.0f)
#define STEP (6.0f / 63.0f)
#define INV_SIG2 2500.0f   // 1 / 0.02^2
#define STRIDE 72          // fp16x2-words per table row: 72%32==8 -> conflict-free
#define TABW (16 * STRIDE) // words per table (16 pixel-pairs)

// Scratch (no allocations allowed)
__device__ float g_part[NB * 3 * NCHUNK * HB * HB];        // 64x64 partial per (b,c,chunk)

__device__ __forceinline__ float kq(float d) {
    float q = fmaf(d * d, INV_SIG2, 1.0f);
    float r;
    asm("rcp.approx.f32 %0, %1;" : "=f"(r) : "f"(q));
    return r;
}

// pack {lo=f0, hi=f1} as fp16x2
__device__ __forceinline__ unsigned pack_h2(float f0, float f1) {
    unsigned r;
    asm("cvt.rn.f16x2.f32 %0, %1, %2;" : "=r"(r) : "f"(f1), "f"(f0));
    return r;
}

// per-pixel prep: clip, logs, intensity (fused into gen; no prep kernel)
__device__ __forceinline__ void pixel_prep(
    const float* __restrict__ xr, const float* __restrict__ xg,
    const float* __restrict__ xb2, int p,
    float& d01, float& d02, float& iy)
{
    float r  = fminf(fmaxf(xr[p],  0.0f), 1.0f);
    float g  = fminf(fmaxf(xg[p],  0.0f), 1.0f);
    float bl = fminf(fmaxf(xb2[p], 0.0f), 1.0f);
    iy = sqrtf(fmaf(r, r, fmaf(g, g, fmaf(bl, bl, 1e-6f))));
    float l0 = __logf(r  + 1e-6f);
    float l1 = __logf(g  + 1e-6f);
    float l2 = __logf(bl + 1e-6f);
    d01 = l0 - l1;
    d02 = l0 - l2;
}

// ---------------------------------------------------------------------------
// Main kernel — per (b, chunk) CTA, ALL 3 channels, fp16 m16n8k16 MMA.
//   Tables per 32-px tile (fp16x2, 2 adjacent pixels packed per word):
//     T0 = iy*K(d01)   [A c0; mirrored A c1]
//     T1 = K(d02)      [B c0; mirrored A c2]
//     T2 = K(d12)      [B c1]
//     T3 = iy*K(d12)   [mirrored B c2]
//   Mirrors use bin index 63-x (kq even + symmetric bins). Double-buffered.
// ---------------------------------------------------------------------------
__device__ __forceinline__ void gen_tile(
    unsigned* __restrict__ buf,
    const float* __restrict__ xr, const float* __restrict__ xg,
    const float* __restrict__ xb2,
    int p0, int tile, int job, int pair, int slot)
{
    int px0 = p0 + tile * 32 + 2 * pair;
    int px1 = px0 + 1;
    int pe  = p0 + CHUNK;
    float a01 = 0.f, a02 = 0.f, aiy = 0.f;
    float b01 = 0.f, b02 = 0.f, biy = 0.f;
    if (px0 < pe) pixel_prep(xr, xg, xb2, px0, a01, a02, aiy);
    if (px1 < pe) pixel_prep(xr, xg, xb2, px1, b01, b02, biy);

    float v0, v1, s0, s1;
    if (job == 0)      { v0 = a01;       v1 = b01;       s0 = aiy; s1 = biy; }
    else if (job == 1) { v0 = a02;       v1 = b02;       s0 = 1.f; s1 = 1.f; }
    else if (job == 2) { v0 = a02 - a01; v1 = b02 - b01; s0 = 1.f; s1 = 1.f; }
    else               { v0 = a02 - a01; v1 = b02 - b01; s0 = aiy; s1 = biy; }

    int bin0 = slot * 16;
    float dB0 = v0 - (LOB + (float)bin0 * STEP);
    float dB1 = v1 - (LOB + (float)bin0 * STEP);
    unsigned h[16];
    #pragma unroll
    for (int i = 0; i < 16; ++i) {
        float k0 = kq(dB0 - (float)i * STEP) * s0;
        float k1 = kq(dB1 - (float)i * STEP) * s1;
        h[i] = pack_h2(k0, k1);
    }
    unsigned* dst = buf + job * TABW + pair * STRIDE + bin0;
    #pragma unroll
    for (int q = 0; q < 4; ++q)
        *reinterpret_cast<uint4*>(dst + 4 * q) =
            make_uint4(h[4*q], h[4*q+1], h[4*q+2], h[4*q+3]);
}

#define HMMA_F16(ACC, A0, A1, A2, A3, B0, B1)                                \
    asm("mma.sync.aligned.m16n8k16.row.col.f32.f16.f16.f32 "                 \
        "{%0,%1,%2,%3}, {%4,%5,%6,%7}, {%8,%9}, {%0,%1,%2,%3};"              \
        : "+f"((ACC)[0]), "+f"((ACC)[1]), "+f"((ACC)[2]), "+f"((ACC)[3])     \
        : "r"(A0), "r"(A1), "r"(A2), "r"(A3), "r"(B0), "r"(B1))

__device__ __forceinline__ void consume_tile(
    const unsigned* __restrict__ buf,
    float acc[3][4][4], int mg, int nb, int gid, int tig)
{
    const unsigned* T0 = buf;
    const unsigned* T1 = buf + TABW;
    const unsigned* T2 = buf + 2 * TABW;
    const unsigned* T3 = buf + 3 * TABW;
    int ub = mg * 16 + gid;       // u-bin (direct)
    int um = 63 - ub;             // u-bin (mirrored); um-8 pairs with ub+8
    #pragma unroll
    for (int kb = 0; kb < 2; ++kb) {
        int r0 = (8 * kb + tig) * STRIDE;
        int r1 = r0 + 4 * STRIDE;
        // c0: A = T0 direct
        unsigned c0a0 = T0[r0 + ub], c0a1 = T0[r0 + ub + 8];
        unsigned c0a2 = T0[r1 + ub], c0a3 = T0[r1 + ub + 8];
        // c1: A = T0 mirrored
        unsigned c1a0 = T0[r0 + um], c1a1 = T0[r0 + um - 8];
        unsigned c1a2 = T0[r1 + um], c1a3 = T0[r1 + um - 8];
        // c2: A = T1 mirrored
        unsigned c2a0 = T1[r0 + um], c2a1 = T1[r0 + um - 8];
        unsigned c2a2 = T1[r1 + um], c2a3 = T1[r1 + um - 8];
        #pragma unroll
        for (int tl = 0; tl < 4; ++tl) {
            int vb = nb + tl * 8 + gid;
            int vm = 63 - vb;
            unsigned b0, b1;
            b0 = T1[r0 + vb]; b1 = T1[r1 + vb];              // c0: B = K02
            HMMA_F16(acc[0][tl], c0a0, c0a1, c0a2, c0a3, b0, b1);
            b0 = T2[r0 + vb]; b1 = T2[r1 + vb];              // c1: B = K12
            HMMA_F16(acc[1][tl], c1a0, c1a1, c1a2, c1a3, b0, b1);
            b0 = T3[r0 + vm]; b1 = T3[r1 + vm];              // c2: B = mirror(iyK12)
            HMMA_F16(acc[2][tl], c2a0, c2a1, c2a2, c2a3, b0, b1);
        }
    }
}

__global__ void __launch_bounds__(TPB, 2) hist_kernel(const float* __restrict__ x) {
    __shared__ unsigned sTab[2][4 * TABW];   // 2 x 18 KB ping-pong

    int cta   = blockIdx.x;           // 0 .. NB*NCHUNK-1
    int chunk = cta % NCHUNK;
    int b     = cta / NCHUNK;

    int t    = threadIdx.x;
    int lane = t & 31;
    int w    = t >> 5;                // warp 0..7
    int gid  = lane >> 2;             // groupID 0..7
    int tig  = lane & 3;              // threadID_in_group 0..3
    int mg   = w >> 1;                // output rows mg*16..
    int nb   = (w & 1) * 32;          // output col base 0 / 32

    // gen mapping: job per warp-pair, 4 threads per (job, pixel-pair) row
    int job  = t >> 6;                // 0..3 (warp-uniform)
    int rem  = t & 63;
    int pair = rem >> 2;              // 0..15
    int slot = rem & 3;               // 16-bin range

    float acc[3][4][4];
    #pragma unroll
    for (int c = 0; c < 3; ++c)
        #pragma unroll
        for (int i = 0; i < 4; ++i)
            #pragma unroll
            for (int j = 0; j < 4; ++j) acc[c][i][j] = 0.0f;

    const float* xr  = x + (size_t)b * 3 * NPIX;
    const float* xg  = xr + NPIX;
    const float* xb2 = xr + 2 * NPIX;
    int p0 = chunk * CHUNK;

    const int NTILES = (CHUNK + 31) / 32;   // 79 (last tile has 4 px)

    gen_tile(sTab[0], xr, xg, xb2, p0, 0, job, pair, slot);
    __syncthreads();

    for (int tile = 0; tile < NTILES; ++tile) {
        int cur = tile & 1;
        int nxt = cur ^ 1;
        if (tile + 1 < NTILES)
            gen_tile(sTab[nxt], xr, xg, xb2, p0, tile + 1, job, pair, slot);
        consume_tile(sTab[cur], acc, mg, nb, gid, tig);
        __syncthreads();
    }

    // write 3 partials (deterministic, no atomics)
    int row0 = mg * 16 + gid;
    #pragma unroll
    for (int c = 0; c < 3; ++c) {
        float* base = g_part + ((size_t)(b * 3 + c) * NCHUNK + chunk) * (HB * HB);
        #pragma unroll
        for (int tl = 0; tl < 4; ++tl) {
            int col = nb + tl * 8 + 2 * tig;
            float2 lo; lo.x = acc[c][tl][0]; lo.y = acc[c][tl][1];
            float2 hi; hi.x = acc[c][tl][2]; hi.y = acc[c][tl][3];
            *reinterpret_cast<float2*>(base + row0 * HB + col)       = lo;
            *reinterpret_cast<float2*>(base + (row0 + 8) * HB + col) = hi;
        }
    }
}

// ---------------------------------------------------------------------------
// Finalize: reduce NCHUNK partials per (b,c), per-batch normalize, write out
// ---------------------------------------------------------------------------
__global__ void __launch_bounds__(TPB) finalize_kernel(float* __restrict__ out) {
    int b = blockIdx.x;
    int t = threadIdx.x;
    float vals[48];
    float local = 0.0f;
    #pragma unroll
    for (int j = 0; j < 48; ++j) {
        int vi = t + TPB * j;            // 0 .. 12287 = c*4096 + u*64 + v
        int c  = vi >> 12;
        int uv = vi & 4095;
        const float* part = g_part + (size_t)(b * 3 + c) * NCHUNK * 4096 + uv;
        float s = 0.0f;
        #pragma unroll
        for (int k = 0; k < NCHUNK; ++k) s += part[k * 4096];
        vals[j] = s;
        local  += s;
    }
    __shared__ float red[TPB];
    red[t] = local;
    __syncthreads();
    #pragma unroll
    for (int s = TPB / 2; s > 0; s >>= 1) {
        if (t < s) red[t] += red[t + s];
        __syncthreads();
    }
    float inv = 1.0f / (red[0] + 1e-6f);
    #pragma unroll
    for (int j = 0; j < 48; ++j) {
        out[(size_t)b * 12288 + t + TPB * j] = vals[j] * inv;
    }
}

// ---------------------------------------------------------------------------
extern "C" void kernel_launch(void* const* d_in, const int* in_sizes, int n_in,
                              void* d_out, int out_size) {
    const float* x = (const float*)d_in[0];
    float* out = (float*)d_out;
    hist_kernel<<<NB * NCHUNK, TPB>>>(x);
    finalize_kernel<<<NB, TPB>>>(out);
}

// round 12
// speedup vs baseline: 1.2228x; 1.2228x over previous
#include <cuda_runtime.h>

#define NPIX 22500
#define NB 32
#define NCHUNK 9
#define CHUNK 2500   // 22500 / 9
#define TPB 256
#define HB 64
#define LOB (-3.0f)
#define STEP (6.0f / 63.0f)
#define INV_SIG2 2500.0f   // 1 / 0.02^2
#define STRIDE 72          // fp16x2-words per table row: 72%32==8 -> conflict-free
#define TABW (16 * STRIDE) // words per table (16 pixel-pairs)

// Scratch (no allocations allowed)
__device__ float g_prep[3 * NB * NPIX];                    // d01, d02, Iy planes
__device__ float g_part[NB * 3 * NCHUNK * HB * HB];        // 64x64 partial per (b,c,chunk)
__device__ float g_hist[NB * 3 * HB * HB];                 // reduced un-normalized hists
__device__ float g_sums[NB * 3];                           // per (b,c) sums

__device__ __forceinline__ float kq(float d) {
    float q = fmaf(d * d, INV_SIG2, 1.0f);
    float r;
    asm("rcp.approx.f32 %0, %1;" : "=f"(r) : "f"(q));
    return r;
}

// pack {lo=f0, hi=f1} as fp16x2
__device__ __forceinline__ unsigned pack_h2(float f0, float f1) {
    unsigned r;
    asm("cvt.rn.f16x2.f32 %0, %1, %2;" : "=r"(r) : "f"(f1), "f"(f0));
    return r;
}

// ---------------------------------------------------------------------------
// Kernel 1: per-pixel prep — clip, logs, intensity
// ---------------------------------------------------------------------------
__global__ void __launch_bounds__(TPB) prep_kernel(const float* __restrict__ x) {
    int idx = blockIdx.x * blockDim.x + threadIdx.x;
    if (idx >= NB * NPIX) return;
    int b = idx / NPIX;
    int p = idx - b * NPIX;
    const float* xb = x + (size_t)b * 3 * NPIX;
    float r  = fminf(fmaxf(xb[p],            0.0f), 1.0f);
    float g  = fminf(fmaxf(xb[NPIX + p],     0.0f), 1.0f);
    float bl = fminf(fmaxf(xb[2 * NPIX + p], 0.0f), 1.0f);
    float iy = sqrtf(fmaf(r, r, fmaf(g, g, fmaf(bl, bl, 1e-6f))));
    float l0 = logf(r  + 1e-6f);
    float l1 = logf(g  + 1e-6f);
    float l2 = logf(bl + 1e-6f);
    g_prep[idx]                 = l0 - l1;   // d01
    g_prep[NB * NPIX + idx]     = l0 - l2;   // d02
    g_prep[2 * NB * NPIX + idx] = iy;
}

// ---------------------------------------------------------------------------
// Kernel 2: main — per (b, chunk) CTA, ALL 3 channels, fp16 m16n8k16 MMA.
//   Tables per 32-px tile (fp16x2, 2 adjacent pixels packed per word):
//     T0 = iy*K(d01)   [A c0; mirrored A c1]
//     T1 = K(d02)      [B c0; mirrored A c2]
//     T2 = K(d12)      [B c1]
//     T3 = iy*K(d12)   [mirrored B c2]  — job 2 writes BOTH T2 and T3
//   Mirrors use bin index 63-x at consume (kq even + symmetric bins).
//   Gen uses 3 jobs x 64 threads (t<192); warps 6-7 skip gen. Double-buffered.
// ---------------------------------------------------------------------------
__device__ __forceinline__ void gen_tile(
    unsigned* __restrict__ buf,
    const float* __restrict__ pd01, const float* __restrict__ pd02,
    const float* __restrict__ piy,
    int p0, int tile, int job, int pair, int slot, bool active)
{
    if (!active) return;
    int px0 = p0 + tile * 32 + 2 * pair;
    int px1 = px0 + 1;
    int pe  = p0 + CHUNK;
    float a01 = 0.f, a02 = 0.f, aiy = 0.f;
    float b01 = 0.f, b02 = 0.f, biy = 0.f;
    if (px0 < pe) { a01 = pd01[px0]; a02 = pd02[px0]; aiy = piy[px0]; }
    if (px1 < pe) { b01 = pd01[px1]; b02 = pd02[px1]; biy = piy[px1]; }

    int bin0 = slot * 16;
    float base = LOB + (float)bin0 * STEP;
    if (job == 0) {             // T0 = iy*K(d01)
        float dB0 = a01 - base, dB1 = b01 - base;
        unsigned h[16];
        #pragma unroll
        for (int i = 0; i < 16; ++i) {
            float k0 = kq(dB0 - (float)i * STEP) * aiy;
            float k1 = kq(dB1 - (float)i * STEP) * biy;
            h[i] = pack_h2(k0, k1);
        }
        unsigned* dst = buf + pair * STRIDE + bin0;
        #pragma unroll
        for (int q = 0; q < 4; ++q)
            *reinterpret_cast<uint4*>(dst + 4 * q) =
                make_uint4(h[4*q], h[4*q+1], h[4*q+2], h[4*q+3]);
    } else if (job == 1) {      // T1 = K(d02)
        float dB0 = a02 - base, dB1 = b02 - base;
        unsigned h[16];
        #pragma unroll
        for (int i = 0; i < 16; ++i) {
            float k0 = kq(dB0 - (float)i * STEP);
            float k1 = kq(dB1 - (float)i * STEP);
            h[i] = pack_h2(k0, k1);
        }
        unsigned* dst = buf + TABW + pair * STRIDE + bin0;
        #pragma unroll
        for (int q = 0; q < 4; ++q)
            *reinterpret_cast<uint4*>(dst + 4 * q) =
                make_uint4(h[4*q], h[4*q+1], h[4*q+2], h[4*q+3]);
    } else {                    // T2 = K(d12), T3 = iy*K(d12) — one rcp set
        float dB0 = (a02 - a01) - base, dB1 = (b02 - b01) - base;
        unsigned hr[16], hs[16];
        #pragma unroll
        for (int i = 0; i < 16; ++i) {
            float k0 = kq(dB0 - (float)i * STEP);
            float k1 = kq(dB1 - (float)i * STEP);
            hr[i] = pack_h2(k0, k1);
            hs[i] = pack_h2(k0 * aiy, k1 * biy);
        }
        unsigned* d2 = buf + 2 * TABW + pair * STRIDE + bin0;
        unsigned* d3 = buf + 3 * TABW + pair * STRIDE + bin0;
        #pragma unroll
        for (int q = 0; q < 4; ++q) {
            *reinterpret_cast<uint4*>(d2 + 4 * q) =
                make_uint4(hr[4*q], hr[4*q+1], hr[4*q+2], hr[4*q+3]);
            *reinterpret_cast<uint4*>(d3 + 4 * q) =
                make_uint4(hs[4*q], hs[4*q+1], hs[4*q+2], hs[4*q+3]);
        }
    }
}

#define HMMA_F16(ACC, A0, A1, A2, A3, B0, B1)                                \
    asm("mma.sync.aligned.m16n8k16.row.col.f32.f16.f16.f32 "                 \
        "{%0,%1,%2,%3}, {%4,%5,%6,%7}, {%8,%9}, {%0,%1,%2,%3};"              \
        : "+f"((ACC)[0]), "+f"((ACC)[1]), "+f"((ACC)[2]), "+f"((ACC)[3])     \
        : "r"(A0), "r"(A1), "r"(A2), "r"(A3), "r"(B0), "r"(B1))

__device__ __forceinline__ void consume_tile(
    const unsigned* __restrict__ buf,
    float acc[3][4][4], int mg, int nb, int gid, int tig)
{
    const unsigned* T0 = buf;
    const unsigned* T1 = buf + TABW;
    const unsigned* T2 = buf + 2 * TABW;
    const unsigned* T3 = buf + 3 * TABW;
    int ub = mg * 16 + gid;       // u-bin (direct)
    int um = 63 - ub;             // u-bin (mirrored); um-8 pairs with ub+8
    #pragma unroll
    for (int kb = 0; kb < 2; ++kb) {
        int r0 = (8 * kb + tig) * STRIDE;
        int r1 = r0 + 4 * STRIDE;
        // c0: A = T0 direct
        unsigned c0a0 = T0[r0 + ub], c0a1 = T0[r0 + ub + 8];
        unsigned c0a2 = T0[r1 + ub], c0a3 = T0[r1 + ub + 8];
        // c1: A = T0 mirrored
        unsigned c1a0 = T0[r0 + um], c1a1 = T0[r0 + um - 8];
        unsigned c1a2 = T0[r1 + um], c1a3 = T0[r1 + um - 8];
        // c2: A = T1 mirrored
        unsigned c2a0 = T1[r0 + um], c2a1 = T1[r0 + um - 8];
        unsigned c2a2 = T1[r1 + um], c2a3 = T1[r1 + um - 8];
        #pragma unroll
        for (int tl = 0; tl < 4; ++tl) {
            int vb = nb + tl * 8 + gid;
            int vm = 63 - vb;
            unsigned b0, b1;
            b0 = T1[r0 + vb]; b1 = T1[r1 + vb];              // c0: B = K02
            HMMA_F16(acc[0][tl], c0a0, c0a1, c0a2, c0a3, b0, b1);
            b0 = T2[r0 + vb]; b1 = T2[r1 + vb];              // c1: B = K12
            HMMA_F16(acc[1][tl], c1a0, c1a1, c1a2, c1a3, b0, b1);
            b0 = T3[r0 + vm]; b1 = T3[r1 + vm];              // c2: B = mirror(iyK12)
            HMMA_F16(acc[2][tl], c2a0, c2a1, c2a2, c2a3, b0, b1);
        }
    }
}

__global__ void __launch_bounds__(TPB, 2) hist_kernel() {
    __shared__ unsigned sTab[2][4 * TABW];   // 2 x 18 KB ping-pong

    int cta   = blockIdx.x;           // 0 .. NB*NCHUNK-1
    int chunk = cta % NCHUNK;
    int b     = cta / NCHUNK;

    int t    = threadIdx.x;
    int lane = t & 31;
    int w    = t >> 5;                // warp 0..7
    int gid  = lane >> 2;             // groupID 0..7
    int tig  = lane & 3;              // threadID_in_group 0..3
    int mg   = w >> 1;                // output rows mg*16..
    int nb   = (w & 1) * 32;          // output col base 0 / 32

    // gen mapping: 3 jobs x 64 threads (t<192); warps 6-7 idle in gen
    bool active = (t < 192);
    int job  = t >> 6;                // 0..2 (warp-pair uniform)
    int rem  = t & 63;
    int pair = rem >> 2;              // 0..15
    int slot = rem & 3;               // 16-bin range

    float acc[3][4][4];
    #pragma unroll
    for (int c = 0; c < 3; ++c)
        #pragma unroll
        for (int i = 0; i < 4; ++i)
            #pragma unroll
            for (int j = 0; j < 4; ++j) acc[c][i][j] = 0.0f;

    const float* pd01 = g_prep + (size_t)b * NPIX;
    const float* pd02 = pd01 + (size_t)NB * NPIX;
    const float* piy  = pd01 + (size_t)2 * NB * NPIX;
    int p0 = chunk * CHUNK;

    const int NTILES = (CHUNK + 31) / 32;   // 79 (last tile has 4 px)

    gen_tile(sTab[0], pd01, pd02, piy, p0, 0, job, pair, slot, active);
    __syncthreads();

    for (int tile = 0; tile < NTILES; ++tile) {
        int cur = tile & 1;
        int nxt = cur ^ 1;
        if (tile + 1 < NTILES)
            gen_tile(sTab[nxt], pd01, pd02, piy, p0, tile + 1, job, pair, slot, active);
        consume_tile(sTab[cur], acc, mg, nb, gid, tig);
        __syncthreads();
    }

    // write 3 partials (deterministic, no atomics)
    int row0 = mg * 16 + gid;
    #pragma unroll
    for (int c = 0; c < 3; ++c) {
        float* base = g_part + ((size_t)(b * 3 + c) * NCHUNK + chunk) * (HB * HB);
        #pragma unroll
        for (int tl = 0; tl < 4; ++tl) {
            int col = nb + tl * 8 + 2 * tig;
            float2 lo; lo.x = acc[c][tl][0]; lo.y = acc[c][tl][1];
            float2 hi; hi.x = acc[c][tl][2]; hi.y = acc[c][tl][3];
            *reinterpret_cast<float2*>(base + row0 * HB + col)       = lo;
            *reinterpret_cast<float2*>(base + (row0 + 8) * HB + col) = hi;
        }
    }
}

// ---------------------------------------------------------------------------
// Kernel 3a: per (b,c) reduce NCHUNK partials + block sum (96 CTAs)
// ---------------------------------------------------------------------------
__global__ void __launch_bounds__(TPB) reduce_kernel() {
    int bc = blockIdx.x;              // 0..95 = b*3+c
    int t  = threadIdx.x;
    const float* part = g_part + (size_t)bc * NCHUNK * 4096;
    float local = 0.0f;
    #pragma unroll
    for (int j = 0; j < 16; ++j) {
        int uv = t + TPB * j;
        float s = 0.0f;
        #pragma unroll
        for (int k = 0; k < NCHUNK; ++k) s += part[k * 4096 + uv];
        g_hist[(size_t)bc * 4096 + uv] = s;
        local += s;
    }
    __shared__ float red[TPB];
    red[t] = local;
    __syncthreads();
    #pragma unroll
    for (int s = TPB / 2; s > 0; s >>= 1) {
        if (t < s) red[t] += red[t + s];
        __syncthreads();
    }
    if (t == 0) g_sums[bc] = red[0];
}

// ---------------------------------------------------------------------------
// Kernel 3b: per (b,c) normalize by per-b total (96 CTAs)
// ---------------------------------------------------------------------------
__global__ void __launch_bounds__(TPB) normalize_kernel(float* __restrict__ out) {
    int bc = blockIdx.x;              // 0..95
    int b  = bc / 3;
    int t  = threadIdx.x;
    float tot = g_sums[b * 3] + g_sums[b * 3 + 1] + g_sums[b * 3 + 2];
    float inv = 1.0f / (tot + 1e-6f);
    const float* src = g_hist + (size_t)bc * 4096;
    float* dst = out + (size_t)b * 12288 + (size_t)(bc % 3) * 4096;
    #pragma unroll
    for (int j = 0; j < 16; ++j) {
        int uv = t + TPB * j;
        dst[uv] = src[uv] * inv;
    }
}

// ---------------------------------------------------------------------------
extern "C" void kernel_launch(void* const* d_in, const int* in_sizes, int n_in,
                              void* d_out, int out_size) {
    const float* x = (const float*)d_in[0];
    float* out = (float*)d_out;
    prep_kernel<<<(NB * NPIX + TPB - 1) / TPB, TPB>>>(x);
    hist_kernel<<<NB * NCHUNK, TPB>>>();
    reduce_kernel<<<NB * 3, TPB>>>();
    normalize_kernel<<<NB * 3, TPB>>>(out);
}

// round 13
// speedup vs baseline: 1.3226x; 1.0816x over previous
#include <cuda_runtime.h>

#define NPIX 22500
#define NB 32
#define NCHUNK 9
#define CHUNK 2500   // 22500 / 9
#define TPB 256
#define HB 64
#define LOB (-3.0f)
#define STEP (6.0f / 63.0f)
#define INV_SIG2 2500.0f   // 1 / 0.02^2
#define STRIDE 72          // fp16x2-words per table row: 72%32==8 -> conflict-free
#define TABW (16 * STRIDE) // words per table (16 pixel-pairs)

// Scratch (no allocations allowed)
__device__ float g_part[NB * 3 * NCHUNK * HB * HB];        // 64x64 partial per (b,c,chunk)
__device__ float g_hist[NB * 3 * HB * HB];                 // reduced un-normalized hists
__device__ float g_sums[NB * 3];                           // per (b,c) sums

__device__ __forceinline__ float kq(float d) {
    float q = fmaf(d * d, INV_SIG2, 1.0f);
    float r;
    asm("rcp.approx.f32 %0, %1;" : "=f"(r) : "f"(q));
    return r;
}

// pack {lo=f0, hi=f1} as fp16x2
__device__ __forceinline__ unsigned pack_h2(float f0, float f1) {
    unsigned r;
    asm("cvt.rn.f16x2.f32 %0, %1, %2;" : "=r"(r) : "f"(f1), "f"(f0));
    return r;
}

// ---------------------------------------------------------------------------
// In-kernel prep: warp 6 stages d01/d02/iy for one 32-px tile into SMEM.
// OOB pixels stage zeros (iy=0 keeps all channel products zero).
// ---------------------------------------------------------------------------
__device__ __forceinline__ void prep_tile(
    const float* __restrict__ xr, const float* __restrict__ xg,
    const float* __restrict__ xb2,
    int p0, int tile, int lane, float* __restrict__ dst /* [96] */)
{
    int p  = p0 + tile * 32 + lane;
    float d01 = 0.f, d02 = 0.f, iy = 0.f;
    if (p < p0 + CHUNK) {
        float r  = fminf(fmaxf(xr[p],  0.0f), 1.0f);
        float g  = fminf(fmaxf(xg[p],  0.0f), 1.0f);
        float bl = fminf(fmaxf(xb2[p], 0.0f), 1.0f);
        iy = sqrtf(fmaf(r, r, fmaf(g, g, fmaf(bl, bl, 1e-6f))));
        float l0 = __logf(r  + 1e-6f);
        float l1 = __logf(g  + 1e-6f);
        float l2 = __logf(bl + 1e-6f);
        d01 = l0 - l1;
        d02 = l0 - l2;
    }
    dst[lane]      = d01;
    dst[32 + lane] = d02;
    dst[64 + lane] = iy;
}

// ---------------------------------------------------------------------------
// Gen: 3 jobs x 64 threads (t<192); reads staged prep values from SMEM.
//   T0 = iy*K(d01), T1 = K(d02), T2 = K(d12), T3 = iy*K(d12) (job2 does both)
// ---------------------------------------------------------------------------
__device__ __forceinline__ void gen_tile(
    unsigned* __restrict__ buf, const float* __restrict__ sp,
    int job, int pair, int slot, bool active)
{
    if (!active) return;
    float a01 = sp[2 * pair],      b01 = sp[2 * pair + 1];
    float a02 = sp[32 + 2 * pair], b02 = sp[32 + 2 * pair + 1];
    float aiy = sp[64 + 2 * pair], biy = sp[64 + 2 * pair + 1];

    int bin0 = slot * 16;
    float base = LOB + (float)bin0 * STEP;
    if (job == 0) {             // T0 = iy*K(d01)
        float dB0 = a01 - base, dB1 = b01 - base;
        unsigned h[16];
        #pragma unroll
        for (int i = 0; i < 16; ++i) {
            float k0 = kq(dB0 - (float)i * STEP) * aiy;
            float k1 = kq(dB1 - (float)i * STEP) * biy;
            h[i] = pack_h2(k0, k1);
        }
        unsigned* dst = buf + pair * STRIDE + bin0;
        #pragma unroll
        for (int q = 0; q < 4; ++q)
            *reinterpret_cast<uint4*>(dst + 4 * q) =
                make_uint4(h[4*q], h[4*q+1], h[4*q+2], h[4*q+3]);
    } else if (job == 1) {      // T1 = K(d02)
        float dB0 = a02 - base, dB1 = b02 - base;
        unsigned h[16];
        #pragma unroll
        for (int i = 0; i < 16; ++i) {
            float k0 = kq(dB0 - (float)i * STEP);
            float k1 = kq(dB1 - (float)i * STEP);
            h[i] = pack_h2(k0, k1);
        }
        unsigned* dst = buf + TABW + pair * STRIDE + bin0;
        #pragma unroll
        for (int q = 0; q < 4; ++q)
            *reinterpret_cast<uint4*>(dst + 4 * q) =
                make_uint4(h[4*q], h[4*q+1], h[4*q+2], h[4*q+3]);
    } else {                    // T2 = K(d12), T3 = iy*K(d12) — one rcp set
        float dB0 = (a02 - a01) - base, dB1 = (b02 - b01) - base;
        unsigned hr[16], hs[16];
        #pragma unroll
        for (int i = 0; i < 16; ++i) {
            float k0 = kq(dB0 - (float)i * STEP);
            float k1 = kq(dB1 - (float)i * STEP);
            hr[i] = pack_h2(k0, k1);
            hs[i] = pack_h2(k0 * aiy, k1 * biy);
        }
        unsigned* d2 = buf + 2 * TABW + pair * STRIDE + bin0;
        unsigned* d3 = buf + 3 * TABW + pair * STRIDE + bin0;
        #pragma unroll
        for (int q = 0; q < 4; ++q) {
            *reinterpret_cast<uint4*>(d2 + 4 * q) =
                make_uint4(hr[4*q], hr[4*q+1], hr[4*q+2], hr[4*q+3]);
            *reinterpret_cast<uint4*>(d3 + 4 * q) =
                make_uint4(hs[4*q], hs[4*q+1], hs[4*q+2], hs[4*q+3]);
        }
    }
}

#define HMMA_F16(ACC, A0, A1, A2, A3, B0, B1)                                \
    asm("mma.sync.aligned.m16n8k16.row.col.f32.f16.f16.f32 "                 \
        "{%0,%1,%2,%3}, {%4,%5,%6,%7}, {%8,%9}, {%0,%1,%2,%3};"              \
        : "+f"((ACC)[0]), "+f"((ACC)[1]), "+f"((ACC)[2]), "+f"((ACC)[3])     \
        : "r"(A0), "r"(A1), "r"(A2), "r"(A3), "r"(B0), "r"(B1))

__device__ __forceinline__ void consume_tile(
    const unsigned* __restrict__ buf,
    float acc[3][4][4], int mg, int nb, int gid, int tig)
{
    const unsigned* T0 = buf;
    const unsigned* T1 = buf + TABW;
    const unsigned* T2 = buf + 2 * TABW;
    const unsigned* T3 = buf + 3 * TABW;
    int ub = mg * 16 + gid;       // u-bin (direct)
    int um = 63 - ub;             // u-bin (mirrored); um-8 pairs with ub+8
    #pragma unroll
    for (int kb = 0; kb < 2; ++kb) {
        int r0 = (8 * kb + tig) * STRIDE;
        int r1 = r0 + 4 * STRIDE;
        // c0: A = T0 direct
        unsigned c0a0 = T0[r0 + ub], c0a1 = T0[r0 + ub + 8];
        unsigned c0a2 = T0[r1 + ub], c0a3 = T0[r1 + ub + 8];
        // c1: A = T0 mirrored
        unsigned c1a0 = T0[r0 + um], c1a1 = T0[r0 + um - 8];
        unsigned c1a2 = T0[r1 + um], c1a3 = T0[r1 + um - 8];
        // c2: A = T1 mirrored
        unsigned c2a0 = T1[r0 + um], c2a1 = T1[r0 + um - 8];
        unsigned c2a2 = T1[r1 + um], c2a3 = T1[r1 + um - 8];
        #pragma unroll
        for (int tl = 0; tl < 4; ++tl) {
            int vb = nb + tl * 8 + gid;
            int vm = 63 - vb;
            unsigned b0, b1;
            b0 = T1[r0 + vb]; b1 = T1[r1 + vb];              // c0: B = K02
            HMMA_F16(acc[0][tl], c0a0, c0a1, c0a2, c0a3, b0, b1);
            b0 = T2[r0 + vb]; b1 = T2[r1 + vb];              // c1: B = K12
            HMMA_F16(acc[1][tl], c1a0, c1a1, c1a2, c1a3, b0, b1);
            b0 = T3[r0 + vm]; b1 = T3[r1 + vm];              // c2: B = mirror(iyK12)
            HMMA_F16(acc[2][tl], c2a0, c2a1, c2a2, c2a3, b0, b1);
        }
    }
}

__global__ void __launch_bounds__(TPB, 2) hist_kernel(const float* __restrict__ x) {
    __shared__ unsigned sTab[2][4 * TABW];   // 2 x 18 KB ping-pong tables
    __shared__ float sPrep[2][96];           // staged d01/d02/iy, 2 tiles

    int cta   = blockIdx.x;           // 0 .. NB*NCHUNK-1
    int chunk = cta % NCHUNK;
    int b     = cta / NCHUNK;

    int t    = threadIdx.x;
    int lane = t & 31;
    int w    = t >> 5;                // warp 0..7
    int gid  = lane >> 2;             // groupID 0..7
    int tig  = lane & 3;              // threadID_in_group 0..3
    int mg   = w >> 1;                // output rows mg*16..
    int nb   = (w & 1) * 32;          // output col base 0 / 32

    // gen mapping: 3 jobs x 64 threads (t<192); warp 6 = prep; warp 7 idle
    bool active = (t < 192);
    int job  = t >> 6;                // 0..2 (warp-pair uniform)
    int rem  = t & 63;
    int pair = rem >> 2;              // 0..15
    int slot = rem & 3;               // 16-bin range

    float acc[3][4][4];
    #pragma unroll
    for (int c = 0; c < 3; ++c)
        #pragma unroll
        for (int i = 0; i < 4; ++i)
            #pragma unroll
            for (int j = 0; j < 4; ++j) acc[c][i][j] = 0.0f;

    const float* xr  = x + (size_t)b * 3 * NPIX;
    const float* xg  = xr + NPIX;
    const float* xb2 = xr + 2 * NPIX;
    int p0 = chunk * CHUNK;

    const int NTILES = (CHUNK + 31) / 32;   // 79 (last tile has 4 px)

    // prologue: stage prep for tiles 0 and 1, then gen tile 0
    if (w == 6) {
        prep_tile(xr, xg, xb2, p0, 0, lane, sPrep[0]);
        prep_tile(xr, xg, xb2, p0, 1, lane, sPrep[1]);
    }
    __syncthreads();
    gen_tile(sTab[0], sPrep[0], job, pair, slot, active);
    __syncthreads();

    for (int tile = 0; tile < NTILES; ++tile) {
        int cur = tile & 1;
        int nxt = cur ^ 1;
        // gen(t+1) reads sPrep[nxt]; prep(t+2) writes sPrep[cur] (free this phase)
        if (tile + 1 < NTILES)
            gen_tile(sTab[nxt], sPrep[nxt], job, pair, slot, active);
        if (w == 6 && tile + 2 < NTILES)
            prep_tile(xr, xg, xb2, p0, tile + 2, lane, sPrep[cur]);
        consume_tile(sTab[cur], acc, mg, nb, gid, tig);
        __syncthreads();
    }

    // write 3 partials (deterministic, no atomics)
    int row0 = mg * 16 + gid;
    #pragma unroll
    for (int c = 0; c < 3; ++c) {
        float* base = g_part + ((size_t)(b * 3 + c) * NCHUNK + chunk) * (HB * HB);
        #pragma unroll
        for (int tl = 0; tl < 4; ++tl) {
            int col = nb + tl * 8 + 2 * tig;
            float2 lo; lo.x = acc[c][tl][0]; lo.y = acc[c][tl][1];
            float2 hi; hi.x = acc[c][tl][2]; hi.y = acc[c][tl][3];
            *reinterpret_cast<float2*>(base + row0 * HB + col)       = lo;
            *reinterpret_cast<float2*>(base + (row0 + 8) * HB + col) = hi;
        }
    }
}

// ---------------------------------------------------------------------------
// Kernel 3a: per (b,c) reduce NCHUNK partials + block sum (96 CTAs)
// ---------------------------------------------------------------------------
__global__ void __launch_bounds__(TPB) reduce_kernel() {
    int bc = blockIdx.x;              // 0..95 = b*3+c
    int t  = threadIdx.x;
    const float* part = g_part + (size_t)bc * NCHUNK * 4096;
    float local = 0.0f;
    #pragma unroll
    for (int j = 0; j < 16; ++j) {
        int uv = t + TPB * j;
        float s = 0.0f;
        #pragma unroll
        for (int k = 0; k < NCHUNK; ++k) s += part[k * 4096 + uv];
        g_hist[(size_t)bc * 4096 + uv] = s;
        local += s;
    }
    __shared__ float red[TPB];
    red[t] = local;
    __syncthreads();
    #pragma unroll
    for (int s = TPB / 2; s > 0; s >>= 1) {
        if (t < s) red[t] += red[t + s];
        __syncthreads();
    }
    if (t == 0) g_sums[bc] = red[0];
}

// ---------------------------------------------------------------------------
// Kernel 3b: per (b,c) normalize by per-b total (96 CTAs)
// ---------------------------------------------------------------------------
__global__ void __launch_bounds__(TPB) normalize_kernel(float* __restrict__ out) {
    int bc = blockIdx.x;              // 0..95
    int b  = bc / 3;
    int t  = threadIdx.x;
    float tot = g_sums[b * 3] + g_sums[b * 3 + 1] + g_sums[b * 3 + 2];
    float inv = 1.0f / (tot + 1e-6f);
    const float* src = g_hist + (size_t)bc * 4096;
    float* dst = out + (size_t)b * 12288 + (size_t)(bc % 3) * 4096;
    #pragma unroll
    for (int j = 0; j < 16; ++j) {
        int uv = t + TPB * j;
        dst[uv] = src[uv] * inv;
    }
}

// ---------------------------------------------------------------------------
extern "C" void kernel_launch(void* const* d_in, const int* in_sizes, int n_in,
                              void* d_out, int out_size) {
    const float* x = (const float*)d_in[0];
    float* out = (float*)d_out;
    hist_kernel<<<NB * NCHUNK, TPB>>>(x);
    reduce_kernel<<<NB * 3, TPB>>>();
    normalize_kernel<<<NB * 3, TPB>>>(out);
}

// round 14
// speedup vs baseline: 1.3639x; 1.0312x over previous
#include <cuda_runtime.h>

#define NPIX 22500
#define NB 32
#define NCHUNK 9
#define CHUNK 2500   // 22500 / 9
#define TPB 256
#define HB 64
#define LOB (-3.0f)
#define STEP (6.0f / 63.0f)
#define INV_SIG2 2500.0f   // 1 / 0.02^2
#define ROWB 144           // bytes per k-row (72 b16): 36 words, bank step 4 -> CF
#define TABB (32 * ROWB)   // 4608 B per table (32 pixel-rows)
#define BUFB (4 * TABB)    // 18432 B per buffer (T0,T1,T2,T3)

// Scratch (no allocations allowed)
__device__ float g_part[NB * 3 * NCHUNK * HB * HB];        // 64x64 partial per (b,c,chunk)
__device__ float g_hist[NB * 3 * HB * HB];                 // reduced un-normalized hists
__device__ float g_sums[NB * 3];                           // per (b,c) sums

__device__ __forceinline__ float kq(float d) {
    float q = fmaf(d * d, INV_SIG2, 1.0f);
    float r;
    asm("rcp.approx.f32 %0, %1;" : "=f"(r) : "f"(q));
    return r;
}

// pack {lo=f0, hi=f1} as fp16x2
__device__ __forceinline__ unsigned pack_h2(float f0, float f1) {
    unsigned r;
    asm("cvt.rn.f16x2.f32 %0, %1, %2;" : "=r"(r) : "f"(f1), "f"(f0));
    return r;
}

// ---------------------------------------------------------------------------
// In-kernel prep: warp 6 stages d01/d02/iy for one 32-px tile into SMEM.
// OOB pixels stage zeros (iy=0 keeps all channel products zero).
// ---------------------------------------------------------------------------
__device__ __forceinline__ void prep_tile(
    const float* __restrict__ xr, const float* __restrict__ xg,
    const float* __restrict__ xb2,
    int p0, int tile, int lane, float* __restrict__ dst /* [96] */)
{
    int p  = p0 + tile * 32 + lane;
    float d01 = 0.f, d02 = 0.f, iy = 0.f;
    if (p < p0 + CHUNK) {
        float r  = fminf(fmaxf(xr[p],  0.0f), 1.0f);
        float g  = fminf(fmaxf(xg[p],  0.0f), 1.0f);
        float bl = fminf(fmaxf(xb2[p], 0.0f), 1.0f);
        iy = sqrtf(fmaf(r, r, fmaf(g, g, fmaf(bl, bl, 1e-6f))));
        float l0 = __logf(r  + 1e-6f);
        float l1 = __logf(g  + 1e-6f);
        float l2 = __logf(bl + 1e-6f);
        d01 = l0 - l1;
        d02 = l0 - l2;
    }
    dst[lane]      = d01;
    dst[32 + lane] = d02;
    dst[64 + lane] = iy;
}

// ---------------------------------------------------------------------------
// Gen: 3 jobs x 64 threads (t<192). Layout: b16 M[k=pixel 0..31][bin 0..63],
// row stride 144 B. Thread = (job, px, half); computes 32 bins for one pixel.
//   job0: T0 = iy*K(d01); job1: T1 = K(d02); job2: T2 = K(d12), T3 = iy*K(d12)
// ---------------------------------------------------------------------------
__device__ __forceinline__ void gen_tile(
    unsigned char* __restrict__ buf, const float* __restrict__ sp,
    int job, int px, int half, bool active)
{
    if (!active) return;
    float d01 = sp[px], d02 = sp[32 + px], iy = sp[64 + px];
    float v = (job == 0) ? d01 : ((job == 1) ? d02 : (d02 - d01));
    float dB = v - (LOB + (float)(half * 32) * STEP);

    unsigned char* d0 = buf + ((job == 2) ? 2 * TABB : (unsigned)job * TABB)
                        + px * ROWB + half * 64;
    #pragma unroll
    for (int q = 0; q < 4; ++q) {
        float kk[8];
        #pragma unroll
        for (int i = 0; i < 8; ++i)
            kk[i] = kq(dB - (float)(8 * q + i) * STEP);
        if (job == 0) {
            uint4 o = make_uint4(pack_h2(kk[0]*iy, kk[1]*iy), pack_h2(kk[2]*iy, kk[3]*iy),
                                 pack_h2(kk[4]*iy, kk[5]*iy), pack_h2(kk[6]*iy, kk[7]*iy));
            *reinterpret_cast<uint4*>(d0 + 16 * q) = o;
        } else if (job == 1) {
            uint4 o = make_uint4(pack_h2(kk[0], kk[1]), pack_h2(kk[2], kk[3]),
                                 pack_h2(kk[4], kk[5]), pack_h2(kk[6], kk[7]));
            *reinterpret_cast<uint4*>(d0 + 16 * q) = o;
        } else {
            uint4 o = make_uint4(pack_h2(kk[0], kk[1]), pack_h2(kk[2], kk[3]),
                                 pack_h2(kk[4], kk[5]), pack_h2(kk[6], kk[7]));
            *reinterpret_cast<uint4*>(d0 + 16 * q) = o;
            uint4 s = make_uint4(pack_h2(kk[0]*iy, kk[1]*iy), pack_h2(kk[2]*iy, kk[3]*iy),
                                 pack_h2(kk[4]*iy, kk[5]*iy), pack_h2(kk[6]*iy, kk[7]*iy));
            *reinterpret_cast<uint4*>(d0 + TABB + 16 * q) = s;  // T3 right after T2
        }
    }
}

#define HMMA_F16(ACC, A0, A1, A2, A3, B0, B1)                                \
    asm("mma.sync.aligned.m16n8k16.row.col.f32.f16.f16.f32 "                 \
        "{%0,%1,%2,%3}, {%4,%5,%6,%7}, {%8,%9}, {%0,%1,%2,%3};"              \
        : "+f"((ACC)[0]), "+f"((ACC)[1]), "+f"((ACC)[2]), "+f"((ACC)[3])     \
        : "r"(A0), "r"(A1), "r"(A2), "r"(A3), "r"(B0), "r"(B1))

__device__ __forceinline__ void ldm4(unsigned& r0, unsigned& r1,
                                     unsigned& r2, unsigned& r3, unsigned a) {
    asm volatile("ldmatrix.sync.aligned.m8n8.x4.trans.shared.b16 {%0,%1,%2,%3}, [%4];"
                 : "=r"(r0), "=r"(r1), "=r"(r2), "=r"(r3) : "r"(a));
}

// Consume: per kb (16 px), A frags for T0,T1 once; B frags per (table, tl-pair).
__device__ __forceinline__ void consume_tile(
    unsigned bufA, float acc[3][4][4], unsigned laneA, unsigned laneB)
{
    #pragma unroll
    for (int kb = 0; kb < 2; ++kb) {
        unsigned ko = (unsigned)kb * (16 * ROWB);
        unsigned a00, a01, a02, a03, a10, a11, a12, a13;
        ldm4(a00, a01, a02, a03, bufA + ko + laneA);              // A = T0 (c0,c1)
        ldm4(a10, a11, a12, a13, bufA + TABB + ko + laneA);       // A = T1 (c2)
        #pragma unroll
        for (int tp = 0; tp < 2; ++tp) {
            unsigned o = ko + laneB + (unsigned)tp * 32;
            unsigned b0, b1, b2, b3;
            ldm4(b0, b1, b2, b3, bufA + TABB + o);                // B = T1 (c0)
            HMMA_F16(acc[0][2*tp],   a00, a01, a02, a03, b0, b1);
            HMMA_F16(acc[0][2*tp+1], a00, a01, a02, a03, b2, b3);
            ldm4(b0, b1, b2, b3, bufA + 2 * TABB + o);            // B = T2 (c1)
            HMMA_F16(acc[1][2*tp],   a00, a01, a02, a03, b0, b1);
            HMMA_F16(acc[1][2*tp+1], a00, a01, a02, a03, b2, b3);
            ldm4(b0, b1, b2, b3, bufA + 3 * TABB + o);            // B = T3 (c2)
            HMMA_F16(acc[2][2*tp],   a10, a11, a12, a13, b0, b1);
            HMMA_F16(acc[2][2*tp+1], a10, a11, a12, a13, b2, b3);
        }
    }
}

__global__ void __launch_bounds__(TPB, 2) hist_kernel(const float* __restrict__ x) {
    __shared__ __align__(16) unsigned char sTab[2][BUFB];   // 2 x 18 KB
    __shared__ float sPrep[2][96];

    int cta   = blockIdx.x;           // 0 .. NB*NCHUNK-1
    int chunk = cta % NCHUNK;
    int b     = cta / NCHUNK;

    int t    = threadIdx.x;
    int lane = t & 31;
    int w    = t >> 5;                // warp 0..7
    int gid  = lane >> 2;             // groupID 0..7
    int tig  = lane & 3;              // threadID_in_group 0..3
    int mg   = w >> 1;                // output rows mg*16..
    int nb   = (w & 1) * 32;          // output col base 0 / 32

    // gen mapping: 3 jobs x 64 threads (t<192); warp 6 = prep; warp 7 idle
    bool active = (t < 192);
    int job  = t >> 6;                // 0..2 (warp-pair uniform)
    int rem  = t & 63;
    int px   = rem >> 1;              // pixel 0..31
    int half = rem & 1;               // bin half (32 bins)

    // ldmatrix per-lane byte offsets (k-row, col): A=(m side), B=(n side)
    unsigned laneA = (unsigned)(((lane & 7) + 8 * (lane >> 4)) * ROWB
                                + mg * 32 + 16 * ((lane >> 3) & 1));
    unsigned laneB = (unsigned)(((lane & 7) + 8 * ((lane >> 3) & 1)) * ROWB
                                + nb * 2 + 16 * (lane >> 4));
    unsigned sT = (unsigned)__cvta_generic_to_shared(&sTab[0][0]);

    float acc[3][4][4];
    #pragma unroll
    for (int c = 0; c < 3; ++c)
        #pragma unroll
        for (int i = 0; i < 4; ++i)
            #pragma unroll
            for (int j = 0; j < 4; ++j) acc[c][i][j] = 0.0f;

    const float* xr  = x + (size_t)b * 3 * NPIX;
    const float* xg  = xr + NPIX;
    const float* xb2 = xr + 2 * NPIX;
    int p0 = chunk * CHUNK;

    const int NTILES = (CHUNK + 31) / 32;   // 79 (last tile has 4 px)

    if (w == 6) {
        prep_tile(xr, xg, xb2, p0, 0, lane, sPrep[0]);
        prep_tile(xr, xg, xb2, p0, 1, lane, sPrep[1]);
    }
    __syncthreads();
    gen_tile(sTab[0], sPrep[0], job, px, half, active);
    __syncthreads();

    for (int tile = 0; tile < NTILES; ++tile) {
        int cur = tile & 1;
        int nxt = cur ^ 1;
        if (tile + 1 < NTILES)
            gen_tile(sTab[nxt], sPrep[nxt], job, px, half, active);
        if (w == 6 && tile + 2 < NTILES)
            prep_tile(xr, xg, xb2, p0, tile + 2, lane, sPrep[cur]);
        consume_tile(sT + (unsigned)cur * BUFB, acc, laneA, laneB);
        __syncthreads();
    }

    // Partials. Mirrors applied via output permutation:
    //   c0 direct; c1: u -> 63-u; c2: u -> 63-u AND v -> 63-v.
    int row0 = mg * 16 + gid;
    float* p0c = g_part + ((size_t)(b * 3 + 0) * NCHUNK + chunk) * 4096;
    float* p1c = g_part + ((size_t)(b * 3 + 1) * NCHUNK + chunk) * 4096;
    float* p2c = g_part + ((size_t)(b * 3 + 2) * NCHUNK + chunk) * 4096;
    #pragma unroll
    for (int tl = 0; tl < 4; ++tl) {
        int col = nb + tl * 8 + 2 * tig;
        float2 v;
        v.x = acc[0][tl][0]; v.y = acc[0][tl][1];
        *reinterpret_cast<float2*>(p0c + row0 * 64 + col) = v;
        v.x = acc[0][tl][2]; v.y = acc[0][tl][3];
        *reinterpret_cast<float2*>(p0c + (row0 + 8) * 64 + col) = v;

        v.x = acc[1][tl][0]; v.y = acc[1][tl][1];
        *reinterpret_cast<float2*>(p1c + (63 - row0) * 64 + col) = v;
        v.x = acc[1][tl][2]; v.y = acc[1][tl][3];
        *reinterpret_cast<float2*>(p1c + (55 - row0) * 64 + col) = v;

        v.x = acc[2][tl][1]; v.y = acc[2][tl][0];
        *reinterpret_cast<float2*>(p2c + (63 - row0) * 64 + (62 - col)) = v;
        v.x = acc[2][tl][3]; v.y = acc[2][tl][2];
        *reinterpret_cast<float2*>(p2c + (55 - row0) * 64 + (62 - col)) = v;
    }
}

// ---------------------------------------------------------------------------
// Kernel 3a: per (b,c) reduce NCHUNK partials + block sum (96 CTAs)
// ---------------------------------------------------------------------------
__global__ void __launch_bounds__(TPB) reduce_kernel() {
    int bc = blockIdx.x;              // 0..95 = b*3+c
    int t  = threadIdx.x;
    const float* part = g_part + (size_t)bc * NCHUNK * 4096;
    float local = 0.0f;
    #pragma unroll
    for (int j = 0; j < 16; ++j) {
        int uv = t + TPB * j;
        float s = 0.0f;
        #pragma unroll
        for (int k = 0; k < NCHUNK; ++k) s += part[k * 4096 + uv];
        g_hist[(size_t)bc * 4096 + uv] = s;
        local += s;
    }
    __shared__ float red[TPB];
    red[t] = local;
    __syncthreads();
    #pragma unroll
    for (int s = TPB / 2; s > 0; s >>= 1) {
        if (t < s) red[t] += red[t + s];
        __syncthreads();
    }
    if (t == 0) g_sums[bc] = red[0];
}

// ---------------------------------------------------------------------------
// Kernel 3b: per (b,c) normalize by per-b total (96 CTAs)
// ---------------------------------------------------------------------------
__global__ void __launch_bounds__(TPB) normalize_kernel(float* __restrict__ out) {
    int bc = blockIdx.x;              // 0..95
    int b  = bc / 3;
    int t  = threadIdx.x;
    float tot = g_sums[b * 3] + g_sums[b * 3 + 1] + g_sums[b * 3 + 2];
    float inv = 1.0f / (tot + 1e-6f);
    const float* src = g_hist + (size_t)bc * 4096;
    float* dst = out + (size_t)b * 12288 + (size_t)(bc % 3) * 4096;
    #pragma unroll
    for (int j = 0; j < 16; ++j) {
        int uv = t + TPB * j;
        dst[uv] = src[uv] * inv;
    }
}

// ---------------------------------------------------------------------------
extern "C" void kernel_launch(void* const* d_in, const int* in_sizes, int n_in,
                              void* d_out, int out_size) {
    const float* x = (const float*)d_in[0];
    float* out = (float*)d_out;
    hist_kernel<<<NB * NCHUNK, TPB>>>(x);
    reduce_kernel<<<NB * 3, TPB>>>();
    normalize_kernel<<<NB * 3, TPB>>>(out);
}

// round 15
// speedup vs baseline: 1.4000x; 1.0265x over previous
#include <cuda_runtime.h>

#define NPIX 22500
#define NB 32
#define NCHUNK 9
#define CHUNK 2500   // 22500 / 9
#define TPB 256
#define HB 64
#define LOB (-3.0f)
#define STEP (6.0f / 63.0f)
#define INV_SIG2 2500.0f   // 1 / 0.02^2
#define TPX 64             // pixels per tile
#define ROWB 144           // bytes per pixel-row (64 b16 bins + pad): bank step 4 -> CF
#define TABB (TPX * ROWB)  // 9216 B per table
#define BUFB (4 * TABB)    // 36864 B per buffer (T0,T1,T2,T3)
// dynamic SMEM layout: [2][BUFB] tables, then [2][192] prep floats
#define PREP_OFF (2 * BUFB)
#define SMEM_TOTAL (PREP_OFF + 2 * 192 * 4)

// Scratch (no allocations allowed)
__device__ float g_part[NB * 3 * NCHUNK * HB * HB];        // 64x64 partial per (b,c,chunk)
__device__ float g_hist[NB * 3 * HB * HB];                 // reduced un-normalized hists
__device__ float g_sums[NB * 3];                           // per (b,c) sums

__device__ __forceinline__ float kq(float d) {
    float q = fmaf(d * d, INV_SIG2, 1.0f);
    float r;
    asm("rcp.approx.f32 %0, %1;" : "=f"(r) : "f"(q));
    return r;
}

// pack {lo=f0, hi=f1} as fp16x2
__device__ __forceinline__ unsigned pack_h2(float f0, float f1) {
    unsigned r;
    asm("cvt.rn.f16x2.f32 %0, %1, %2;" : "=r"(r) : "f"(f1), "f"(f0));
    return r;
}

// ---------------------------------------------------------------------------
// In-kernel prep: warps 6+7 stage d01/d02/iy for one 64-px tile into SMEM.
// OOB pixels stage zeros (iy=0 keeps all channel products zero).
// ---------------------------------------------------------------------------
__device__ __forceinline__ void prep_tile(
    const float* __restrict__ xr, const float* __restrict__ xg,
    const float* __restrict__ xb2,
    int p0, int tile, int px, float* __restrict__ dst /* [192] */)
{
    int p  = p0 + tile * TPX + px;
    float d01 = 0.f, d02 = 0.f, iy = 0.f;
    if (p < p0 + CHUNK) {
        float r  = fminf(fmaxf(xr[p],  0.0f), 1.0f);
        float g  = fminf(fmaxf(xg[p],  0.0f), 1.0f);
        float bl = fminf(fmaxf(xb2[p], 0.0f), 1.0f);
        iy = sqrtf(fmaf(r, r, fmaf(g, g, fmaf(bl, bl, 1e-6f))));
        float l0 = __logf(r  + 1e-6f);
        float l1 = __logf(g  + 1e-6f);
        float l2 = __logf(bl + 1e-6f);
        d01 = l0 - l1;
        d02 = l0 - l2;
    }
    dst[px]        = d01;
    dst[64 + px]   = d02;
    dst[128 + px]  = iy;
}

// ---------------------------------------------------------------------------
// Gen: 3 jobs x 64 threads (t<192). Layout: b16 M[k=pixel 0..63][bin 0..63],
// row stride 144 B. Thread = (job, px); computes all 64 bins for one pixel.
//   job0: T0 = iy*K(d01); job1: T1 = K(d02); job2: T2 = K(d12), T3 = iy*K(d12)
// ---------------------------------------------------------------------------
__device__ __forceinline__ void gen_tile(
    unsigned char* __restrict__ buf, const float* __restrict__ sp,
    int job, int px, bool active)
{
    if (!active) return;
    float d01 = sp[px], d02 = sp[64 + px], iy = sp[128 + px];
    float v = (job == 0) ? d01 : ((job == 1) ? d02 : (d02 - d01));
    float dB = v - LOB;

    unsigned char* d0 = buf + ((job == 2) ? 2 * TABB : (unsigned)job * TABB)
                        + px * ROWB;
    #pragma unroll
    for (int q = 0; q < 8; ++q) {
        float kk[8];
        #pragma unroll
        for (int i = 0; i < 8; ++i)
            kk[i] = kq(dB - (float)(8 * q + i) * STEP);
        if (job == 0) {
            uint4 o = make_uint4(pack_h2(kk[0]*iy, kk[1]*iy), pack_h2(kk[2]*iy, kk[3]*iy),
                                 pack_h2(kk[4]*iy, kk[5]*iy), pack_h2(kk[6]*iy, kk[7]*iy));
            *reinterpret_cast<uint4*>(d0 + 16 * q) = o;
        } else if (job == 1) {
            uint4 o = make_uint4(pack_h2(kk[0], kk[1]), pack_h2(kk[2], kk[3]),
                                 pack_h2(kk[4], kk[5]), pack_h2(kk[6], kk[7]));
            *reinterpret_cast<uint4*>(d0 + 16 * q) = o;
        } else {
            uint4 o = make_uint4(pack_h2(kk[0], kk[1]), pack_h2(kk[2], kk[3]),
                                 pack_h2(kk[4], kk[5]), pack_h2(kk[6], kk[7]));
            *reinterpret_cast<uint4*>(d0 + 16 * q) = o;
            uint4 s = make_uint4(pack_h2(kk[0]*iy, kk[1]*iy), pack_h2(kk[2]*iy, kk[3]*iy),
                                 pack_h2(kk[4]*iy, kk[5]*iy), pack_h2(kk[6]*iy, kk[7]*iy));
            *reinterpret_cast<uint4*>(d0 + TABB + 16 * q) = s;  // T3 right after T2
        }
    }
}

#define HMMA_F16(ACC, A0, A1, A2, A3, B0, B1)                                \
    asm("mma.sync.aligned.m16n8k16.row.col.f32.f16.f16.f32 "                 \
        "{%0,%1,%2,%3}, {%4,%5,%6,%7}, {%8,%9}, {%0,%1,%2,%3};"              \
        : "+f"((ACC)[0]), "+f"((ACC)[1]), "+f"((ACC)[2]), "+f"((ACC)[3])     \
        : "r"(A0), "r"(A1), "r"(A2), "r"(A3), "r"(B0), "r"(B1))

__device__ __forceinline__ void ldm4(unsigned& r0, unsigned& r1,
                                     unsigned& r2, unsigned& r3, unsigned a) {
    asm volatile("ldmatrix.sync.aligned.m8n8.x4.trans.shared.b16 {%0,%1,%2,%3}, [%4];"
                 : "=r"(r0), "=r"(r1), "=r"(r2), "=r"(r3) : "r"(a));
}

// Consume: per kb (16 px), A frags for T0,T1 once; B frags per (table, tl-pair).
__device__ __forceinline__ void consume_tile(
    unsigned bufA, float acc[3][4][4], unsigned laneA, unsigned laneB)
{
    #pragma unroll
    for (int kb = 0; kb < 4; ++kb) {
        unsigned ko = (unsigned)kb * (16 * ROWB);
        unsigned a00, a01, a02, a03, a10, a11, a12, a13;
        ldm4(a00, a01, a02, a03, bufA + ko + laneA);              // A = T0 (c0,c1)
        ldm4(a10, a11, a12, a13, bufA + TABB + ko + laneA);       // A = T1 (c2)
        #pragma unroll
        for (int tp = 0; tp < 2; ++tp) {
            unsigned o = ko + laneB + (unsigned)tp * 32;
            unsigned b0, b1, b2, b3;
            ldm4(b0, b1, b2, b3, bufA + TABB + o);                // B = T1 (c0)
            HMMA_F16(acc[0][2*tp],   a00, a01, a02, a03, b0, b1);
            HMMA_F16(acc[0][2*tp+1], a00, a01, a02, a03, b2, b3);
            ldm4(b0, b1, b2, b3, bufA + 2 * TABB + o);            // B = T2 (c1)
            HMMA_F16(acc[1][2*tp],   a00, a01, a02, a03, b0, b1);
            HMMA_F16(acc[1][2*tp+1], a00, a01, a02, a03, b2, b3);
            ldm4(b0, b1, b2, b3, bufA + 3 * TABB + o);            // B = T3 (c2)
            HMMA_F16(acc[2][2*tp],   a10, a11, a12, a13, b0, b1);
            HMMA_F16(acc[2][2*tp+1], a10, a11, a12, a13, b2, b3);
        }
    }
}

__global__ void __launch_bounds__(TPB, 2) hist_kernel(const float* __restrict__ x) {
    extern __shared__ __align__(16) unsigned char smem[];
    float* sPrep0 = reinterpret_cast<float*>(smem + PREP_OFF);
    float* sPrep1 = sPrep0 + 192;

    int cta   = blockIdx.x;           // 0 .. NB*NCHUNK-1
    int chunk = cta % NCHUNK;
    int b     = cta / NCHUNK;

    int t    = threadIdx.x;
    int lane = t & 31;
    int w    = t >> 5;                // warp 0..7
    int gid  = lane >> 2;             // groupID 0..7
    int tig  = lane & 3;              // threadID_in_group 0..3
    int mg   = w >> 1;                // output rows mg*16..
    int nb   = (w & 1) * 32;          // output col base 0 / 32

    // gen mapping: 3 jobs x 64 threads (t<192); warps 6+7 = prep
    bool active = (t < 192);
    int job  = t >> 6;                // 0..2 (warp-pair uniform)
    int gpx  = t & 63;                // pixel 0..63
    int ppx  = (w >= 6) ? ((w - 6) * 32 + lane) : 0;  // prep pixel

    // ldmatrix per-lane byte offsets (k-row, col): A=(m side), B=(n side)
    unsigned laneA = (unsigned)(((lane & 7) + 8 * (lane >> 4)) * ROWB
                                + mg * 32 + 16 * ((lane >> 3) & 1));
    unsigned laneB = (unsigned)(((lane & 7) + 8 * ((lane >> 3) & 1)) * ROWB
                                + nb * 2 + 16 * (lane >> 4));
    unsigned sT = (unsigned)__cvta_generic_to_shared(&smem[0]);

    float acc[3][4][4];
    #pragma unroll
    for (int c = 0; c < 3; ++c)
        #pragma unroll
        for (int i = 0; i < 4; ++i)
            #pragma unroll
            for (int j = 0; j < 4; ++j) acc[c][i][j] = 0.0f;

    const float* xr  = x + (size_t)b * 3 * NPIX;
    const float* xg  = xr + NPIX;
    const float* xb2 = xr + 2 * NPIX;
    int p0 = chunk * CHUNK;

    const int NTILES = (CHUNK + TPX - 1) / TPX;   // 40 (last tile has 4 px)

    if (w >= 6) {
        prep_tile(xr, xg, xb2, p0, 0, ppx, sPrep0);
        prep_tile(xr, xg, xb2, p0, 1, ppx, sPrep1);
    }
    __syncthreads();
    gen_tile(smem, sPrep0, job, gpx, active);
    __syncthreads();

    for (int tile = 0; tile < NTILES; ++tile) {
        int cur = tile & 1;
        int nxt = cur ^ 1;
        if (tile + 1 < NTILES)
            gen_tile(smem + (unsigned)nxt * BUFB,
                     nxt ? sPrep1 : sPrep0, job, gpx, active);
        if (w >= 6 && tile + 2 < NTILES)
            prep_tile(xr, xg, xb2, p0, tile + 2, ppx, cur ? sPrep1 : sPrep0);
        consume_tile(sT + (unsigned)cur * BUFB, acc, laneA, laneB);
        __syncthreads();
    }

    // Partials. Mirrors applied via output permutation:
    //   c0 direct; c1: u -> 63-u; c2: u -> 63-u AND v -> 63-v.
    int row0 = mg * 16 + gid;
    float* p0c = g_part + ((size_t)(b * 3 + 0) * NCHUNK + chunk) * 4096;
    float* p1c = g_part + ((size_t)(b * 3 + 1) * NCHUNK + chunk) * 4096;
    float* p2c = g_part + ((size_t)(b * 3 + 2) * NCHUNK + chunk) * 4096;
    #pragma unroll
    for (int tl = 0; tl < 4; ++tl) {
        int col = nb + tl * 8 + 2 * tig;
        float2 v;
        v.x = acc[0][tl][0]; v.y = acc[0][tl][1];
        *reinterpret_cast<float2*>(p0c + row0 * 64 + col) = v;
        v.x = acc[0][tl][2]; v.y = acc[0][tl][3];
        *reinterpret_cast<float2*>(p0c + (row0 + 8) * 64 + col) = v;

        v.x = acc[1][tl][0]; v.y = acc[1][tl][1];
        *reinterpret_cast<float2*>(p1c + (63 - row0) * 64 + col) = v;
        v.x = acc[1][tl][2]; v.y = acc[1][tl][3];
        *reinterpret_cast<float2*>(p1c + (55 - row0) * 64 + col) = v;

        v.x = acc[2][tl][1]; v.y = acc[2][tl][0];
        *reinterpret_cast<float2*>(p2c + (63 - row0) * 64 + (62 - col)) = v;
        v.x = acc[2][tl][3]; v.y = acc[2][tl][2];
        *reinterpret_cast<float2*>(p2c + (55 - row0) * 64 + (62 - col)) = v;
    }
}

// ---------------------------------------------------------------------------
// Kernel 3a: per (b,c) reduce NCHUNK partials + block sum (96 CTAs)
// ---------------------------------------------------------------------------
__global__ void __launch_bounds__(TPB) reduce_kernel() {
    int bc = blockIdx.x;              // 0..95 = b*3+c
    int t  = threadIdx.x;
    const float* part = g_part + (size_t)bc * NCHUNK * 4096;
    float local = 0.0f;
    #pragma unroll
    for (int j = 0; j < 16; ++j) {
        int uv = t + TPB * j;
        float s = 0.0f;
        #pragma unroll
        for (int k = 0; k < NCHUNK; ++k) s += part[k * 4096 + uv];
        g_hist[(size_t)bc * 4096 + uv] = s;
        local += s;
    }
    __shared__ float red[TPB];
    red[t] = local;
    __syncthreads();
    #pragma unroll
    for (int s = TPB / 2; s > 0; s >>= 1) {
        if (t < s) red[t] += red[t + s];
        __syncthreads();
    }
    if (t == 0) g_sums[bc] = red[0];
}

// ---------------------------------------------------------------------------
// Kernel 3b: per (b,c) normalize by per-b total (96 CTAs)
// ---------------------------------------------------------------------------
__global__ void __launch_bounds__(TPB) normalize_kernel(float* __restrict__ out) {
    int bc = blockIdx.x;              // 0..95
    int b  = bc / 3;
    int t  = threadIdx.x;
    float tot = g_sums[b * 3] + g_sums[b * 3 + 1] + g_sums[b * 3 + 2];
    float inv = 1.0f / (tot + 1e-6f);
    const float* src = g_hist + (size_t)bc * 4096;
    float* dst = out + (size_t)b * 12288 + (size_t)(bc % 3) * 4096;
    #pragma unroll
    for (int j = 0; j < 16; ++j) {
        int uv = t + TPB * j;
        dst[uv] = src[uv] * inv;
    }
}

// ---------------------------------------------------------------------------
extern "C" void kernel_launch(void* const* d_in, const int* in_sizes, int n_in,
                              void* d_out, int out_size) {
    const float* x = (const float*)d_in[0];
    float* out = (float*)d_out;
    static int configured = 0;
    if (!configured) {
        cudaFuncSetAttribute(hist_kernel,
                             cudaFuncAttributeMaxDynamicSharedMemorySize,
                             SMEM_TOTAL);
        configured = 1;
    }
    hist_kernel<<<NB * NCHUNK, TPB, SMEM_TOTAL>>>(x);
    reduce_kernel<<<NB * 3, TPB>>>();
    normalize_kernel<<<NB * 3, TPB>>>(out);
}

// round 16
// speedup vs baseline: 1.5413x; 1.1009x over previous
#include <cuda_runtime.h>

#define NPIX 22500
#define NB 32
#define NCHUNK 9
#define CHUNK 2500   // 22500 / 9
#define TPB 512
#define HB 64
#define LOB (-3.0f)
#define STEP (6.0f / 63.0f)
#define INV_SIG2 2500.0f   // 1 / 0.02^2
#define TPX 64             // pixels per tile
#define ROWB 144           // bytes per pixel-row (64 b16 bins + pad): bank step 4 -> CF
#define TABB (TPX * ROWB)  // 9216 B per table
#define BUFB (4 * TABB)    // 36864 B per buffer (T0,T1,T2,T3)
// dynamic SMEM layout: [2][BUFB] tables, then [2][192] prep floats
#define PREP_OFF (2 * BUFB)
#define SMEM_TOTAL (PREP_OFF + 2 * 192 * 4)

// Scratch (no allocations allowed)
__device__ float g_part[NB * 3 * NCHUNK * HB * HB];        // 64x64 partial per (b,c,chunk)
__device__ float g_hist[NB * 3 * HB * HB];                 // reduced un-normalized hists
__device__ float g_sums[NB * 3];                           // per (b,c) sums

__device__ __forceinline__ float kq(float d) {
    float q = fmaf(d * d, INV_SIG2, 1.0f);
    float r;
    asm("rcp.approx.f32 %0, %1;" : "=f"(r) : "f"(q));
    return r;
}

// pack {lo=f0, hi=f1} as fp16x2
__device__ __forceinline__ unsigned pack_h2(float f0, float f1) {
    unsigned r;
    asm("cvt.rn.f16x2.f32 %0, %1, %2;" : "=r"(r) : "f"(f1), "f"(f0));
    return r;
}

// ---------------------------------------------------------------------------
// In-kernel prep: threads 384-447 stage d01/d02/iy for one 64-px tile.
// OOB pixels stage zeros (iy=0 keeps all channel products zero).
// ---------------------------------------------------------------------------
__device__ __forceinline__ void prep_tile(
    const float* __restrict__ xr, const float* __restrict__ xg,
    const float* __restrict__ xb2,
    int p0, int tile, int px, float* __restrict__ dst /* [192] */)
{
    int p  = p0 + tile * TPX + px;
    float d01 = 0.f, d02 = 0.f, iy = 0.f;
    if (p < p0 + CHUNK) {
        float r  = fminf(fmaxf(xr[p],  0.0f), 1.0f);
        float g  = fminf(fmaxf(xg[p],  0.0f), 1.0f);
        float bl = fminf(fmaxf(xb2[p], 0.0f), 1.0f);
        iy = sqrtf(fmaf(r, r, fmaf(g, g, fmaf(bl, bl, 1e-6f))));
        float l0 = __logf(r  + 1e-6f);
        float l1 = __logf(g  + 1e-6f);
        float l2 = __logf(bl + 1e-6f);
        d01 = l0 - l1;
        d02 = l0 - l2;
    }
    dst[px]        = d01;
    dst[64 + px]   = d02;
    dst[128 + px]  = iy;
}

// ---------------------------------------------------------------------------
// Gen: 3 jobs x 128 threads (t<384). Thread = (job, px, half): 32 bins.
//   job0: T0 = iy*K(d01); job1: T1 = K(d02); job2: T2 = K(d12), T3 = iy*K(d12)
// ---------------------------------------------------------------------------
__device__ __forceinline__ void gen_tile(
    unsigned char* __restrict__ buf, const float* __restrict__ sp,
    int job, int px, int half, bool active)
{
    if (!active) return;
    float d01 = sp[px], d02 = sp[64 + px], iy = sp[128 + px];
    float v = (job == 0) ? d01 : ((job == 1) ? d02 : (d02 - d01));
    float dB = v - (LOB + (float)(half * 32) * STEP);

    unsigned char* d0 = buf + ((job == 2) ? 2 * TABB : (unsigned)job * TABB)
                        + px * ROWB + half * 64;
    #pragma unroll
    for (int q = 0; q < 4; ++q) {
        float kk[8];
        #pragma unroll
        for (int i = 0; i < 8; ++i)
            kk[i] = kq(dB - (float)(8 * q + i) * STEP);
        if (job == 0) {
            uint4 o = make_uint4(pack_h2(kk[0]*iy, kk[1]*iy), pack_h2(kk[2]*iy, kk[3]*iy),
                                 pack_h2(kk[4]*iy, kk[5]*iy), pack_h2(kk[6]*iy, kk[7]*iy));
            *reinterpret_cast<uint4*>(d0 + 16 * q) = o;
        } else if (job == 1) {
            uint4 o = make_uint4(pack_h2(kk[0], kk[1]), pack_h2(kk[2], kk[3]),
                                 pack_h2(kk[4], kk[5]), pack_h2(kk[6], kk[7]));
            *reinterpret_cast<uint4*>(d0 + 16 * q) = o;
        } else {
            uint4 o = make_uint4(pack_h2(kk[0], kk[1]), pack_h2(kk[2], kk[3]),
                                 pack_h2(kk[4], kk[5]), pack_h2(kk[6], kk[7]));
            *reinterpret_cast<uint4*>(d0 + 16 * q) = o;
            uint4 s = make_uint4(pack_h2(kk[0]*iy, kk[1]*iy), pack_h2(kk[2]*iy, kk[3]*iy),
                                 pack_h2(kk[4]*iy, kk[5]*iy), pack_h2(kk[6]*iy, kk[7]*iy));
            *reinterpret_cast<uint4*>(d0 + TABB + 16 * q) = s;  // T3 right after T2
        }
    }
}

#define HMMA_F16(ACC, A0, A1, A2, A3, B0, B1)                                \
    asm("mma.sync.aligned.m16n8k16.row.col.f32.f16.f16.f32 "                 \
        "{%0,%1,%2,%3}, {%4,%5,%6,%7}, {%8,%9}, {%0,%1,%2,%3};"              \
        : "+f"((ACC)[0]), "+f"((ACC)[1]), "+f"((ACC)[2]), "+f"((ACC)[3])     \
        : "r"(A0), "r"(A1), "r"(A2), "r"(A3), "r"(B0), "r"(B1))

__device__ __forceinline__ void ldm4(unsigned& r0, unsigned& r1,
                                     unsigned& r2, unsigned& r3, unsigned a) {
    asm volatile("ldmatrix.sync.aligned.m8n8.x4.trans.shared.b16 {%0,%1,%2,%3}, [%4];"
                 : "=r"(r0), "=r"(r1), "=r"(r2), "=r"(r3) : "r"(a));
}

// Consume: 16 warps; each owns a 16x16 output block (mg, nbq) for 3 channels.
// Per kb: A frags for T0 (c0,c1) + T1 (c2); B frags (n16) for T1, T2, T3.
__device__ __forceinline__ void consume_tile(
    unsigned bufA, float acc[3][2][4], unsigned laneA, unsigned laneB)
{
    #pragma unroll
    for (int kb = 0; kb < 4; ++kb) {
        unsigned ko = (unsigned)kb * (16 * ROWB);
        unsigned a00, a01, a02, a03, a10, a11, a12, a13;
        ldm4(a00, a01, a02, a03, bufA + ko + laneA);              // A = T0 (c0,c1)
        ldm4(a10, a11, a12, a13, bufA + TABB + ko + laneA);       // A = T1 (c2)
        unsigned o = ko + laneB;
        unsigned b0, b1, b2, b3;
        ldm4(b0, b1, b2, b3, bufA + TABB + o);                    // B = T1 (c0)
        HMMA_F16(acc[0][0], a00, a01, a02, a03, b0, b1);
        HMMA_F16(acc[0][1], a00, a01, a02, a03, b2, b3);
        ldm4(b0, b1, b2, b3, bufA + 2 * TABB + o);                // B = T2 (c1)
        HMMA_F16(acc[1][0], a00, a01, a02, a03, b0, b1);
        HMMA_F16(acc[1][1], a00, a01, a02, a03, b2, b3);
        ldm4(b0, b1, b2, b3, bufA + 3 * TABB + o);                // B = T3 (c2)
        HMMA_F16(acc[2][0], a10, a11, a12, a13, b0, b1);
        HMMA_F16(acc[2][1], a10, a11, a12, a13, b2, b3);
    }
}

__global__ void __launch_bounds__(TPB, 2) hist_kernel(const float* __restrict__ x) {
    extern __shared__ __align__(16) unsigned char smem[];
    float* sPrep0 = reinterpret_cast<float*>(smem + PREP_OFF);
    float* sPrep1 = sPrep0 + 192;

    int cta   = blockIdx.x;           // 0 .. NB*NCHUNK-1
    int chunk = cta % NCHUNK;
    int b     = cta / NCHUNK;

    int t    = threadIdx.x;
    int lane = t & 31;
    int w    = t >> 5;                // warp 0..15
    int gid  = lane >> 2;             // groupID 0..7
    int tig  = lane & 3;              // threadID_in_group 0..3
    int mg   = w >> 2;                // output rows mg*16..
    int nbq  = w & 3;                 // output col base nbq*16

    // gen mapping: 3 jobs x 128 threads (t<384); t 384-447 = prep
    bool active = (t < 384);
    int job  = t >> 7;                // 0..2 (warp-quad uniform)
    int rem  = t & 127;
    int gpx  = rem >> 1;              // pixel 0..63
    int half = rem & 1;               // bin half
    int ppx  = t & 63;                // prep pixel (for t in [384,448))
    bool isPrep = (t >= 384 && t < 448);

    // ldmatrix per-lane byte offsets (k-row, col): A=(m side), B=(n side)
    unsigned laneA = (unsigned)(((lane & 7) + 8 * (lane >> 4)) * ROWB
                                + mg * 32 + 16 * ((lane >> 3) & 1));
    unsigned laneB = (unsigned)(((lane & 7) + 8 * ((lane >> 3) & 1)) * ROWB
                                + nbq * 32 + 16 * (lane >> 4));
    unsigned sT = (unsigned)__cvta_generic_to_shared(&smem[0]);

    float acc[3][2][4];
    #pragma unroll
    for (int c = 0; c < 3; ++c)
        #pragma unroll
        for (int i = 0; i < 2; ++i)
            #pragma unroll
            for (int j = 0; j < 4; ++j) acc[c][i][j] = 0.0f;

    const float* xr  = x + (size_t)b * 3 * NPIX;
    const float* xg  = xr + NPIX;
    const float* xb2 = xr + 2 * NPIX;
    int p0 = chunk * CHUNK;

    const int NTILES = (CHUNK + TPX - 1) / TPX;   // 40 (last tile has 4 px)

    if (isPrep) {
        prep_tile(xr, xg, xb2, p0, 0, ppx, sPrep0);
        prep_tile(xr, xg, xb2, p0, 1, ppx, sPrep1);
    }
    __syncthreads();
    gen_tile(smem, sPrep0, job, gpx, half, active);
    __syncthreads();

    for (int tile = 0; tile < NTILES; ++tile) {
        int cur = tile & 1;
        int nxt = cur ^ 1;
        if (tile + 1 < NTILES)
            gen_tile(smem + (unsigned)nxt * BUFB,
                     nxt ? sPrep1 : sPrep0, job, gpx, half, active);
        if (isPrep && tile + 2 < NTILES)
            prep_tile(xr, xg, xb2, p0, tile + 2, ppx, cur ? sPrep1 : sPrep0);
        consume_tile(sT + (unsigned)cur * BUFB, acc, laneA, laneB);
        __syncthreads();
    }

    // Partials. Mirrors applied via output permutation:
    //   c0 direct; c1: u -> 63-u; c2: u -> 63-u AND v -> 63-v.
    int row0 = mg * 16 + gid;
    float* p0c = g_part + ((size_t)(b * 3 + 0) * NCHUNK + chunk) * 4096;
    float* p1c = g_part + ((size_t)(b * 3 + 1) * NCHUNK + chunk) * 4096;
    float* p2c = g_part + ((size_t)(b * 3 + 2) * NCHUNK + chunk) * 4096;
    #pragma unroll
    for (int tl = 0; tl < 2; ++tl) {
        int col = nbq * 16 + tl * 8 + 2 * tig;
        float2 v;
        v.x = acc[0][tl][0]; v.y = acc[0][tl][1];
        *reinterpret_cast<float2*>(p0c + row0 * 64 + col) = v;
        v.x = acc[0][tl][2]; v.y = acc[0][tl][3];
        *reinterpret_cast<float2*>(p0c + (row0 + 8) * 64 + col) = v;

        v.x = acc[1][tl][0]; v.y = acc[1][tl][1];
        *reinterpret_cast<float2*>(p1c + (63 - row0) * 64 + col) = v;
        v.x = acc[1][tl][2]; v.y = acc[1][tl][3];
        *reinterpret_cast<float2*>(p1c + (55 - row0) * 64 + col) = v;

        v.x = acc[2][tl][1]; v.y = acc[2][tl][0];
        *reinterpret_cast<float2*>(p2c + (63 - row0) * 64 + (62 - col)) = v;
        v.x = acc[2][tl][3]; v.y = acc[2][tl][2];
        *reinterpret_cast<float2*>(p2c + (55 - row0) * 64 + (62 - col)) = v;
    }
}

// ---------------------------------------------------------------------------
// Kernel 3a: per (b,c) reduce NCHUNK partials + block sum (96 CTAs)
// ---------------------------------------------------------------------------
__global__ void __launch_bounds__(256) reduce_kernel() {
    int bc = blockIdx.x;              // 0..95 = b*3+c
    int t  = threadIdx.x;
    const float* part = g_part + (size_t)bc * NCHUNK * 4096;
    float local = 0.0f;
    #pragma unroll
    for (int j = 0; j < 16; ++j) {
        int uv = t + 256 * j;
        float s = 0.0f;
        #pragma unroll
        for (int k = 0; k < NCHUNK; ++k) s += part[k * 4096 + uv];
        g_hist[(size_t)bc * 4096 + uv] = s;
        local += s;
    }
    __shared__ float red[256];
    red[t] = local;
    __syncthreads();
    #pragma unroll
    for (int s = 128; s > 0; s >>= 1) {
        if (t < s) red[t] += red[t + s];
        __syncthreads();
    }
    if (t == 0) g_sums[bc] = red[0];
}

// ---------------------------------------------------------------------------
// Kernel 3b: per (b,c) normalize by per-b total (96 CTAs)
// ---------------------------------------------------------------------------
__global__ void __launch_bounds__(256) normalize_kernel(float* __restrict__ out) {
    int bc = blockIdx.x;              // 0..95
    int b  = bc / 3;
    int t  = threadIdx.x;
    float tot = g_sums[b * 3] + g_sums[b * 3 + 1] + g_sums[b * 3 + 2];
    float inv = 1.0f / (tot + 1e-6f);
    const float* src = g_hist + (size_t)bc * 4096;
    float* dst = out + (size_t)b * 12288 + (size_t)(bc % 3) * 4096;
    #pragma unroll
    for (int j = 0; j < 16; ++j) {
        int uv = t + 256 * j;
        dst[uv] = src[uv] * inv;
    }
}

// ---------------------------------------------------------------------------
extern "C" void kernel_launch(void* const* d_in, const int* in_sizes, int n_in,
                              void* d_out, int out_size) {
    const float* x = (const float*)d_in[0];
    float* out = (float*)d_out;
    static int configured = 0;
    if (!configured) {
        cudaFuncSetAttribute(hist_kernel,
                             cudaFuncAttributeMaxDynamicSharedMemorySize,
                             SMEM_TOTAL);
        configured = 1;
    }
    hist_kernel<<<NB * NCHUNK, TPB, SMEM_TOTAL>>>(x);
    reduce_kernel<<<NB * 3, 256>>>();
    normalize_kernel<<<NB * 3, 256>>>(out);
}

// round 17
// speedup vs baseline: 1.5972x; 1.0363x over previous
#include <cuda_runtime.h>

#define NPIX 22500
#define NB 32
#define NCHUNK 9
#define CHUNK 2500   // 22500 / 9
#define TPB 512
#define HB 64
#define LOB (-3.0f)
#define STEP (6.0f / 63.0f)
#define INV_SIG2 2500.0f   // 1 / 0.02^2
#define TPX 64             // pixels per tile
#define ROWB 144           // bytes per pixel-row (64 b16 bins + pad): bank step 4 -> CF
#define TABB (TPX * ROWB)  // 9216 B per table
#define BUFB (4 * TABB)    // 36864 B per buffer (T0, T1, T2, T1s)
// dynamic SMEM layout: [2][BUFB] tables, then [2][192] prep floats
#define PREP_OFF (2 * BUFB)
#define SMEM_TOTAL (PREP_OFF + 2 * 192 * 4)

// Scratch (no allocations allowed)
__device__ float g_part[NB * 3 * NCHUNK * HB * HB];        // 64x64 partial per (b,c,chunk)
__device__ float g_hist[NB * 3 * HB * HB];                 // reduced un-normalized hists
__device__ float g_sums[NB * 3];                           // per (b,c) sums

__device__ __forceinline__ float kq(float d) {
    float q = fmaf(d * d, INV_SIG2, 1.0f);
    float r;
    asm("rcp.approx.f32 %0, %1;" : "=f"(r) : "f"(q));
    return r;
}

// pack {lo=f0, hi=f1} as fp16x2
__device__ __forceinline__ unsigned pack_h2(float f0, float f1) {
    unsigned r;
    asm("cvt.rn.f16x2.f32 %0, %1, %2;" : "=r"(r) : "f"(f1), "f"(f0));
    return r;
}

// ---------------------------------------------------------------------------
// In-kernel prep: threads 384-447 stage d01/d02/iy for one 64-px tile.
// OOB pixels stage zeros (iy=0 keeps all channel products zero).
// ---------------------------------------------------------------------------
__device__ __forceinline__ void prep_tile(
    const float* __restrict__ xr, const float* __restrict__ xg,
    const float* __restrict__ xb2,
    int p0, int tile, int px, float* __restrict__ dst /* [192] */)
{
    int p  = p0 + tile * TPX + px;
    float d01 = 0.f, d02 = 0.f, iy = 0.f;
    if (p < p0 + CHUNK) {
        float r  = fminf(fmaxf(xr[p],  0.0f), 1.0f);
        float g  = fminf(fmaxf(xg[p],  0.0f), 1.0f);
        float bl = fminf(fmaxf(xb2[p], 0.0f), 1.0f);
        iy = sqrtf(fmaf(r, r, fmaf(g, g, fmaf(bl, bl, 1e-6f))));
        float l0 = __logf(r  + 1e-6f);
        float l1 = __logf(g  + 1e-6f);
        float l2 = __logf(bl + 1e-6f);
        d01 = l0 - l1;
        d02 = l0 - l2;
    }
    dst[px]        = d01;
    dst[64 + px]   = d02;
    dst[128 + px]  = iy;
}

// ---------------------------------------------------------------------------
// Gen: 3 jobs x 128 threads (t<384). Thread = (job, px, half): 32 bins.
//   job0: T0  = iy*K(d01)                    @ 0
//   job1: T1  = K(d02) @ TABB,  T1s = iy*K(d02) @ 3*TABB   (one rcp set)
//   job2: T2  = K(d12)                        @ 2*TABB
// ---------------------------------------------------------------------------
__device__ __forceinline__ void gen_tile(
    unsigned char* __restrict__ buf, const float* __restrict__ sp,
    int job, int px, int half, bool active)
{
    if (!active) return;
    float d01 = sp[px], d02 = sp[64 + px], iy = sp[128 + px];
    float v = (job == 0) ? d01 : ((job == 1) ? d02 : (d02 - d01));
    float dB = v - (LOB + (float)(half * 32) * STEP);

    unsigned char* d0 = buf + (unsigned)job * TABB + px * ROWB + half * 64;
    #pragma unroll
    for (int q = 0; q < 4; ++q) {
        float kk[8];
        #pragma unroll
        for (int i = 0; i < 8; ++i)
            kk[i] = kq(dB - (float)(8 * q + i) * STEP);
        if (job == 0) {
            uint4 o = make_uint4(pack_h2(kk[0]*iy, kk[1]*iy), pack_h2(kk[2]*iy, kk[3]*iy),
                                 pack_h2(kk[4]*iy, kk[5]*iy), pack_h2(kk[6]*iy, kk[7]*iy));
            *reinterpret_cast<uint4*>(d0 + 16 * q) = o;
        } else if (job == 1) {
            uint4 o = make_uint4(pack_h2(kk[0], kk[1]), pack_h2(kk[2], kk[3]),
                                 pack_h2(kk[4], kk[5]), pack_h2(kk[6], kk[7]));
            *reinterpret_cast<uint4*>(d0 + 16 * q) = o;
            uint4 s = make_uint4(pack_h2(kk[0]*iy, kk[1]*iy), pack_h2(kk[2]*iy, kk[3]*iy),
                                 pack_h2(kk[4]*iy, kk[5]*iy), pack_h2(kk[6]*iy, kk[7]*iy));
            *reinterpret_cast<uint4*>(d0 + 2 * TABB + 16 * q) = s;  // T1s @ 3*TABB
        } else {
            uint4 o = make_uint4(pack_h2(kk[0], kk[1]), pack_h2(kk[2], kk[3]),
                                 pack_h2(kk[4], kk[5]), pack_h2(kk[6], kk[7]));
            *reinterpret_cast<uint4*>(d0 + 16 * q) = o;
        }
    }
}

#define HMMA_F16(ACC, A0, A1, A2, A3, B0, B1)                                \
    asm("mma.sync.aligned.m16n8k16.row.col.f32.f16.f16.f32 "                 \
        "{%0,%1,%2,%3}, {%4,%5,%6,%7}, {%8,%9}, {%0,%1,%2,%3};"              \
        : "+f"((ACC)[0]), "+f"((ACC)[1]), "+f"((ACC)[2]), "+f"((ACC)[3])     \
        : "r"(A0), "r"(A1), "r"(A2), "r"(A3), "r"(B0), "r"(B1))

__device__ __forceinline__ void ldm4(unsigned& r0, unsigned& r1,
                                     unsigned& r2, unsigned& r3, unsigned a) {
    asm volatile("ldmatrix.sync.aligned.m8n8.x4.trans.shared.b16 {%0,%1,%2,%3}, [%4];"
                 : "=r"(r0), "=r"(r1), "=r"(r2), "=r"(r3) : "r"(a));
}

// Consume: 16 warps; each owns a 16x16 output block (mg, nbq) for 3 channels.
// Per kb: 4 ldm4 (A: T0, T1s; B: T1, T2), 6 HMMA:
//   c0 = T0*T1ᵀ, c1 = T0*T2ᵀ, c2' = T1s*T2ᵀ
__device__ __forceinline__ void consume_tile(
    unsigned bufA, float acc[3][2][4], unsigned laneA, unsigned laneB)
{
    #pragma unroll
    for (int kb = 0; kb < 4; ++kb) {
        unsigned ko = (unsigned)kb * (16 * ROWB);
        unsigned a00, a01, a02, a03, a10, a11, a12, a13;
        ldm4(a00, a01, a02, a03, bufA + ko + laneA);              // A = T0 (c0,c1)
        ldm4(a10, a11, a12, a13, bufA + 3 * TABB + ko + laneA);   // A = T1s (c2)
        unsigned o = ko + laneB;
        unsigned b0, b1, b2, b3, e0, e1, e2, e3;
        ldm4(b0, b1, b2, b3, bufA + TABB + o);                    // B = T1 (c0)
        ldm4(e0, e1, e2, e3, bufA + 2 * TABB + o);                // B = T2 (c1,c2)
        HMMA_F16(acc[0][0], a00, a01, a02, a03, b0, b1);
        HMMA_F16(acc[0][1], a00, a01, a02, a03, b2, b3);
        HMMA_F16(acc[1][0], a00, a01, a02, a03, e0, e1);
        HMMA_F16(acc[1][1], a00, a01, a02, a03, e2, e3);
        HMMA_F16(acc[2][0], a10, a11, a12, a13, e0, e1);
        HMMA_F16(acc[2][1], a10, a11, a12, a13, e2, e3);
    }
}

__global__ void __launch_bounds__(TPB, 2) hist_kernel(const float* __restrict__ x) {
    extern __shared__ __align__(16) unsigned char smem[];
    float* sPrep0 = reinterpret_cast<float*>(smem + PREP_OFF);
    float* sPrep1 = sPrep0 + 192;

    int cta   = blockIdx.x;           // 0 .. NB*NCHUNK-1
    int chunk = cta % NCHUNK;
    int b     = cta / NCHUNK;

    int t    = threadIdx.x;
    int lane = t & 31;
    int w    = t >> 5;                // warp 0..15
    int gid  = lane >> 2;             // groupID 0..7
    int tig  = lane & 3;              // threadID_in_group 0..3
    int mg   = w >> 2;                // output rows mg*16..
    int nbq  = w & 3;                 // output col base nbq*16

    // gen mapping: 3 jobs x 128 threads (t<384); t 384-447 = prep
    bool active = (t < 384);
    int job  = t >> 7;                // 0..2 (warp-quad uniform)
    int rem  = t & 127;
    int gpx  = rem >> 1;              // pixel 0..63
    int half = rem & 1;               // bin half
    int ppx  = t & 63;                // prep pixel (for t in [384,448))
    bool isPrep = (t >= 384 && t < 448);

    // ldmatrix per-lane byte offsets (k-row, col): A=(m side), B=(n side)
    unsigned laneA = (unsigned)(((lane & 7) + 8 * (lane >> 4)) * ROWB
                                + mg * 32 + 16 * ((lane >> 3) & 1));
    unsigned laneB = (unsigned)(((lane & 7) + 8 * ((lane >> 3) & 1)) * ROWB
                                + nbq * 32 + 16 * (lane >> 4));
    unsigned sT = (unsigned)__cvta_generic_to_shared(&smem[0]);

    float acc[3][2][4];
    #pragma unroll
    for (int c = 0; c < 3; ++c)
        #pragma unroll
        for (int i = 0; i < 2; ++i)
            #pragma unroll
            for (int j = 0; j < 4; ++j) acc[c][i][j] = 0.0f;

    const float* xr  = x + (size_t)b * 3 * NPIX;
    const float* xg  = xr + NPIX;
    const float* xb2 = xr + 2 * NPIX;
    int p0 = chunk * CHUNK;

    const int NTILES = (CHUNK + TPX - 1) / TPX;   // 40 (last tile has 4 px)

    if (isPrep) {
        prep_tile(xr, xg, xb2, p0, 0, ppx, sPrep0);
        prep_tile(xr, xg, xb2, p0, 1, ppx, sPrep1);
    }
    __syncthreads();
    gen_tile(smem, sPrep0, job, gpx, half, active);
    __syncthreads();

    for (int tile = 0; tile < NTILES; ++tile) {
        int cur = tile & 1;
        int nxt = cur ^ 1;
        if (tile + 1 < NTILES)
            gen_tile(smem + (unsigned)nxt * BUFB,
                     nxt ? sPrep1 : sPrep0, job, gpx, half, active);
        if (isPrep && tile + 2 < NTILES)
            prep_tile(xr, xg, xb2, p0, tile + 2, ppx, cur ? sPrep1 : sPrep0);
        consume_tile(sT + (unsigned)cur * BUFB, acc, laneA, laneB);
        __syncthreads();
    }

    // Partials. Mirrors applied via output permutation:
    //   c0 direct; c1: u -> 63-u; c2: u -> 63-u AND v -> 63-v.
    int row0 = mg * 16 + gid;
    float* p0c = g_part + ((size_t)(b * 3 + 0) * NCHUNK + chunk) * 4096;
    float* p1c = g_part + ((size_t)(b * 3 + 1) * NCHUNK + chunk) * 4096;
    float* p2c = g_part + ((size_t)(b * 3 + 2) * NCHUNK + chunk) * 4096;
    #pragma unroll
    for (int tl = 0; tl < 2; ++tl) {
        int col = nbq * 16 + tl * 8 + 2 * tig;
        float2 v;
        v.x = acc[0][tl][0]; v.y = acc[0][tl][1];
        *reinterpret_cast<float2*>(p0c + row0 * 64 + col) = v;
        v.x = acc[0][tl][2]; v.y = acc[0][tl][3];
        *reinterpret_cast<float2*>(p0c + (row0 + 8) * 64 + col) = v;

        v.x = acc[1][tl][0]; v.y = acc[1][tl][1];
        *reinterpret_cast<float2*>(p1c + (63 - row0) * 64 + col) = v;
        v.x = acc[1][tl][2]; v.y = acc[1][tl][3];
        *reinterpret_cast<float2*>(p1c + (55 - row0) * 64 + col) = v;

        v.x = acc[2][tl][1]; v.y = acc[2][tl][0];
        *reinterpret_cast<float2*>(p2c + (63 - row0) * 64 + (62 - col)) = v;
        v.x = acc[2][tl][3]; v.y = acc[2][tl][2];
        *reinterpret_cast<float2*>(p2c + (55 - row0) * 64 + (62 - col)) = v;
    }
}

// ---------------------------------------------------------------------------
// Kernel 3a: per (b,c) reduce NCHUNK partials + block sum (96 CTAs)
// ---------------------------------------------------------------------------
__global__ void __launch_bounds__(256) reduce_kernel() {
    int bc = blockIdx.x;              // 0..95 = b*3+c
    int t  = threadIdx.x;
    const float* part = g_part + (size_t)bc * NCHUNK * 4096;
    float local = 0.0f;
    #pragma unroll
    for (int j = 0; j < 16; ++j) {
        int uv = t + 256 * j;
        float s = 0.0f;
        #pragma unroll
        for (int k = 0; k < NCHUNK; ++k) s += part[k * 4096 + uv];
        g_hist[(size_t)bc * 4096 + uv] = s;
        local += s;
    }
    __shared__ float red[256];
    red[t] = local;
    __syncthreads();
    #pragma unroll
    for (int s = 128; s > 0; s >>= 1) {
        if (t < s) red[t] += red[t + s];
        __syncthreads();
    }
    if (t == 0) g_sums[bc] = red[0];
}

// ---------------------------------------------------------------------------
// Kernel 3b: per (b,c) normalize by per-b total (96 CTAs)
// ---------------------------------------------------------------------------
__global__ void __launch_bounds__(256) normalize_kernel(float* __restrict__ out) {
    int bc = blockIdx.x;              // 0..95
    int b  = bc / 3;
    int t  = threadIdx.x;
    float tot = g_sums[b * 3] + g_sums[b * 3 + 1] + g_sums[b * 3 + 2];
    float inv = 1.0f / (tot + 1e-6f);
    const float* src = g_hist + (size_t)bc * 4096;
    float* dst = out + (size_t)b * 12288 + (size_t)(bc % 3) * 4096;
    #pragma unroll
    for (int j = 0; j < 16; ++j) {
        int uv = t + 256 * j;
        dst[uv] = src[uv] * inv;
    }
}

// ---------------------------------------------------------------------------
extern "C" void kernel_launch(void* const* d_in, const int* in_sizes, int n_in,
                              void* d_out, int out_size) {
    const float* x = (const float*)d_in[0];
    float* out = (float*)d_out;
    static int configured = 0;
    if (!configured) {
        cudaFuncSetAttribute(hist_kernel,
                             cudaFuncAttributeMaxDynamicSharedMemorySize,
                             SMEM_TOTAL);
        configured = 1;
    }
    hist_kernel<<<NB * NCHUNK, TPB, SMEM_TOTAL>>>(x);
    reduce_kernel<<<NB * 3, 256>>>();
    normalize_kernel<<<NB * 3, 256>>>(out);
}